// round 5
// baseline (speedup 1.0000x reference)
#include <cuda_runtime.h>
#include <math.h>
#include <stdint.h>

#define Bz 32
#define Tz 1024
#define Dz 256
#define Hz 256
#define NG 1024  // 4*H

// ---------------- scratch (device globals: no allocation allowed) ----------
__device__ __align__(16) float g_xp1[2][Tz][Bz][NG];   // layer1 gate preacts
__device__ __align__(16) float g_xp2[2][Tz][Bz][NG];   // layer2 gate preacts
__device__ __align__(16) float g_h1 [2][Tz][Bz][Hz];   // layer1 hidden states (orig-time)
__device__ __align__(16) float g_hbuf1[2][2][Bz*Hz];   // ping-pong h, layer1
__device__ __align__(16) float g_hbuf2[2][2][Bz*Hz];   // ping-pong h, layer2
__device__ __align__(16) float g_Wt[6][1024][256];     // transposed weights [n][k]
__device__ unsigned int g_flag[4][64 * 8];             // barrier flags, 32B stride

// ---------------- helpers ----------------------------------------------------
__device__ __forceinline__ void st_release(unsigned int* p, unsigned int v) {
    asm volatile("st.global.release.gpu.u32 [%0], %1;" :: "l"(p), "r"(v) : "memory");
}
__device__ __forceinline__ unsigned int ld_acquire(unsigned int* p) {
    unsigned int v;
    asm volatile("ld.global.acquire.gpu.u32 %0, [%1];" : "=r"(v) : "l"(p) : "memory");
    return v;
}
__device__ __forceinline__ float fast_sigmoid(float x) {
    return __fdividef(1.f, 1.f + __expf(-x));
}
__device__ __forceinline__ uint32_t f2tf32(float f) {
    uint32_t u;
    asm("cvt.rna.tf32.f32 %0, %1;" : "=r"(u) : "f"(f));
    return u;
}
__device__ __forceinline__ void mma_tf32(float* d, const uint32_t* a, const uint32_t* b) {
    asm volatile(
        "mma.sync.aligned.m16n8k8.row.col.f32.tf32.tf32.f32 "
        "{%0,%1,%2,%3}, {%4,%5,%6,%7}, {%8,%9}, {%0,%1,%2,%3};"
        : "+f"(d[0]), "+f"(d[1]), "+f"(d[2]), "+f"(d[3])
        : "r"(a[0]), "r"(a[1]), "r"(a[2]), "r"(a[3]), "r"(b[0]), "r"(b[1]));
}

// ---------------- init -------------------------------------------------------
__global__ void k_init() {
    int tid = blockIdx.x * blockDim.x + threadIdx.x;
    if (tid < 4 * 64 * 8) ((unsigned int*)g_flag)[tid] = 0u;
    if (tid < Bz * Hz) {
        g_hbuf1[0][0][tid] = 0.f;
        g_hbuf1[1][0][tid] = 0.f;
        g_hbuf2[0][0][tid] = 0.f;
        g_hbuf2[1][0][tid] = 0.f;
    }
}

// ---------------- weight transpose: Wt[tsr][g*256+h][d] = W[g][d][h] ---------
__global__ void k_transpose(const float* W0, const float* W1, const float* W2,
                            const float* W3, const float* W4, const float* W5) {
    int z = blockIdx.z;
    int tsr = z >> 2, g = z & 3;
    const float* W;
    switch (tsr) {
        case 0: W = W0; break; case 1: W = W1; break; case 2: W = W2; break;
        case 3: W = W3; break; case 4: W = W4; break; default: W = W5; break;
    }
    __shared__ float tile[32][33];
    int h0 = blockIdx.x * 32, d0 = blockIdx.y * 32;
    int tx = threadIdx.x, ty = threadIdx.y;
#pragma unroll
    for (int i = 0; i < 4; ++i) {
        int r = ty + i * 8;
        tile[r][tx] = W[(size_t)g * 65536 + (size_t)(d0 + r) * 256 + h0 + tx];
    }
    __syncthreads();
    float* out = &g_Wt[tsr][0][0];
#pragma unroll
    for (int i = 0; i < 4; ++i) {
        int r = ty + i * 8;
        out[(size_t)(g * 256 + h0 + r) * 256 + d0 + tx] = tile[tx][r];
    }
}

// ---------------- tensor-core GEMM via mma.sync tf32 -------------------------
// tile: M=128 (m = t*32+b), N=128, BK=32. warp tile 64x32 (2x4 warp grid).
// smem A: [k][m] (uint tf32 bits), stride 132; smem B: [k][n], stride 132.
#define SSTR 132
__global__ void __launch_bounds__(256, 2) k_gemm_mma(
    const float* __restrict__ x,
    const float* __restrict__ bias0, const float* __restrict__ bias1,
    int layer)
{
    __shared__ uint32_t As[32 * SSTR];
    __shared__ uint32_t Bs[32 * SSTR];

    const int dir = blockIdx.z;
    const int m0 = blockIdx.y * 128, n0 = blockIdx.x * 128;
    const float* hsrc = &g_h1[dir][0][0][0];
    float* out = (layer == 1) ? &g_xp1[dir][0][0][0] : &g_xp2[dir][0][0][0];
    const float* bias = dir ? bias1 : bias0;
    const float* WtX = &g_Wt[(layer == 1) ? dir : 2 + dir][0][0];
    const float* WtH = &g_Wt[4 + dir][0][0];
    const int NC = (layer == 1) ? 8 : 16;

    const int tid = threadIdx.x, wid = tid >> 5, lane = tid & 31;
    const int wm = (wid >> 2) * 64;     // warp m offset (0 or 64)
    const int wn = (wid & 3) * 32;      // warp n offset (0,32,64,96)
    const int kq = lane & 3, rq = lane >> 2;

    float acc[4][4][4];
#pragma unroll
    for (int mf = 0; mf < 4; ++mf)
#pragma unroll
        for (int nf = 0; nf < 4; ++nf)
#pragma unroll
            for (int r = 0; r < 4; ++r) acc[mf][nf][r] = 0.f;

    // loader indices
    const int lrow = tid >> 3;            // 0..31 per 256-thread pass -> row/8
    const int lk4  = (tid & 7) * 4;       // k quad

    for (int c = 0; c < NC; ++c) {
        const bool isH = (c >= 8);
        const int kc = (c & 7) * 32;
        const float* Wt = isH ? WtH : WtX;

        // A tile: 128 rows (m) x 32 k  -> As[k][m]
#pragma unroll
        for (int i = 0; i < 4; ++i) {
            int row = lrow + i * 32;
            int m = m0 + row, t = m >> 5, bb = m & 31;
            int tt = dir ? (Tz - 1 - t) : t;
            const float* ap = isH ? hsrc + ((size_t)tt * 32 + bb) * 256 + kc + lk4
                                  : x + ((size_t)bb * Tz + tt) * 256 + kc + lk4;
            float4 v = *(const float4*)ap;
            As[(lk4 + 0) * SSTR + row] = f2tf32(v.x);
            As[(lk4 + 1) * SSTR + row] = f2tf32(v.y);
            As[(lk4 + 2) * SSTR + row] = f2tf32(v.z);
            As[(lk4 + 3) * SSTR + row] = f2tf32(v.w);
        }
        // B tile: 128 n-rows x 32 k -> Bs[k][n]
#pragma unroll
        for (int i = 0; i < 4; ++i) {
            int nr = lrow + i * 32;
            float4 v = *(const float4*)(Wt + (size_t)(n0 + nr) * 256 + kc + lk4);
            Bs[(lk4 + 0) * SSTR + nr] = f2tf32(v.x);
            Bs[(lk4 + 1) * SSTR + nr] = f2tf32(v.y);
            Bs[(lk4 + 2) * SSTR + nr] = f2tf32(v.z);
            Bs[(lk4 + 3) * SSTR + nr] = f2tf32(v.w);
        }
        __syncthreads();

#pragma unroll
        for (int ks = 0; ks < 4; ++ks) {
            const int kb = (ks * 8 + kq) * SSTR;
            uint32_t a[4][4], b[4][2];
#pragma unroll
            for (int mf = 0; mf < 4; ++mf) {
                int mi = wm + mf * 16 + rq;
                a[mf][0] = As[kb + mi];
                a[mf][1] = As[kb + mi + 8];
                a[mf][2] = As[kb + 4 * SSTR + mi];
                a[mf][3] = As[kb + 4 * SSTR + mi + 8];
            }
#pragma unroll
            for (int nf = 0; nf < 4; ++nf) {
                int ni = wn + nf * 8 + rq;
                b[nf][0] = Bs[kb + ni];
                b[nf][1] = Bs[kb + 4 * SSTR + ni];
            }
#pragma unroll
            for (int mf = 0; mf < 4; ++mf)
#pragma unroll
                for (int nf = 0; nf < 4; ++nf)
                    mma_tf32(acc[mf][nf], a[mf], b[nf]);
        }
        __syncthreads();
    }

    // epilogue: c0/c1 -> (row, 2*kq), (row, 2*kq+1); c2/c3 -> row+8
#pragma unroll
    for (int nf = 0; nf < 4; ++nf) {
        int n = n0 + wn + nf * 8 + 2 * kq;
        float bx = 0.f, by = 0.f;
        if (layer == 1) { bx = bias[n]; by = bias[n + 1]; }
#pragma unroll
        for (int mf = 0; mf < 4; ++mf) {
            int m = m0 + wm + mf * 16 + rq;
            float2 v0 = make_float2(acc[mf][nf][0] + bx, acc[mf][nf][1] + by);
            float2 v1 = make_float2(acc[mf][nf][2] + bx, acc[mf][nf][3] + by);
            *(float2*)&out[(size_t)m * NG + n]       = v0;
            *(float2*)&out[(size_t)(m + 8) * NG + n] = v1;
        }
    }
}

// ---------------- layer1 recurrence (persistent, flag barrier) ---------------
__global__ void __launch_bounds__(256) k_recur1(
    const float* __restrict__ Uf, const float* __restrict__ Ub)
{
    const int dir = blockIdx.x >> 6;
    const int cg  = blockIdx.x & 63;
    const float* U  = dir ? Ub : Uf;
    const float* xp = &g_xp1[dir][0][0][0];
    float* hs  = &g_h1[dir][0][0][0];
    float* hb0 = g_hbuf1[dir][0];
    float* hb1 = g_hbuf1[dir][1];
    unsigned int* flags = &g_flag[dir][0];

    __shared__ __align__(16) float sU[256][16];
    __shared__ float sPart[8][16][32];

    const int tid = threadIdx.x, lane = tid & 31, w = tid >> 5;

    for (int i = tid; i < 4096; i += 256) {
        int k = i >> 4, gc = i & 15;
        sU[k][gc] = U[(size_t)(gc >> 2) * 65536 + (size_t)k * 256 + cg * 4 + (gc & 3)];
    }
    __syncthreads();

    float c_state = 0.f;
    const int cb = tid >> 2, coc = tid & 3;
    const int outcol = cg * 4 + coc;

    for (int t = 0; t < Tz; ++t) {
        const float* hrd = (t & 1) ? hb1 : hb0;
        float* hwr       = (t & 1) ? hb0 : hb1;

        float xq0 = 0.f, xq1 = 0.f, xq2 = 0.f, xq3 = 0.f;
        if (tid < 128) {
            size_t xb = ((size_t)t * 32 + cb) * NG + outcol;
            xq0 = xp[xb]; xq1 = xp[xb + 256]; xq2 = xp[xb + 512]; xq3 = xp[xb + 768];
        }

        float hreg[32];
        const float4* hp = (const float4*)(hrd + lane * 256 + w * 32);
#pragma unroll
        for (int j = 0; j < 8; ++j) {
            float4 v = hp[j];
            hreg[4*j] = v.x; hreg[4*j+1] = v.y; hreg[4*j+2] = v.z; hreg[4*j+3] = v.w;
        }

        float acc[16];
#pragma unroll
        for (int c = 0; c < 16; ++c) acc[c] = 0.f;
#pragma unroll
        for (int k = 0; k < 32; ++k) {
            int kk = w * 32 + k;
            float4 u0 = *(const float4*)&sU[kk][0];
            float4 u1 = *(const float4*)&sU[kk][4];
            float4 u2 = *(const float4*)&sU[kk][8];
            float4 u3 = *(const float4*)&sU[kk][12];
            float h = hreg[k];
            acc[0]+=u0.x*h; acc[1]+=u0.y*h; acc[2]+=u0.z*h; acc[3]+=u0.w*h;
            acc[4]+=u1.x*h; acc[5]+=u1.y*h; acc[6]+=u1.z*h; acc[7]+=u1.w*h;
            acc[8]+=u2.x*h; acc[9]+=u2.y*h; acc[10]+=u2.z*h; acc[11]+=u2.w*h;
            acc[12]+=u3.x*h; acc[13]+=u3.y*h; acc[14]+=u3.z*h; acc[15]+=u3.w*h;
        }
#pragma unroll
        for (int c = 0; c < 16; ++c) sPart[w][c][lane] = acc[c];
        __syncthreads();

        if (tid < 128) {
            float p0 = xq0, p1 = xq1, p2 = xq2, p3 = xq3;
#pragma unroll
            for (int ww = 0; ww < 8; ++ww) {
                p0 += sPart[ww][0  + coc][cb];
                p1 += sPart[ww][4  + coc][cb];
                p2 += sPart[ww][8  + coc][cb];
                p3 += sPart[ww][12 + coc][cb];
            }
            float ig = fast_sigmoid(p0);
            float fg = fast_sigmoid(p1);
            float gg = fast_sigmoid(p2);
            float og = fast_sigmoid(p3);
            c_state = fg + c_state + ig * gg;
            float hn = og + tanhf(c_state);
            hwr[cb * 256 + outcol] = hn;
            int tout = dir ? (Tz - 1 - t) : t;
            hs[((size_t)tout * 32 + cb) * 256 + outcol] = hn;
        }
        __syncthreads();
        if (tid == 0) st_release(&flags[cg * 8], (unsigned)t + 1);
        if (tid < 64) {
            while (ld_acquire(&flags[tid * 8]) <= (unsigned)t) { }
        }
        __syncthreads();
    }
}

// ---------------- layer2 recurrence ------------------------------------------
__global__ void __launch_bounds__(256) k_recur2(
    const float* __restrict__ Uf, const float* __restrict__ Ub,
    const float* __restrict__ b2f, const float* __restrict__ b2b,
    float* __restrict__ dout)
{
    const int dir = blockIdx.x >> 6;
    const int cg  = blockIdx.x & 63;
    const float* U  = dir ? Ub : Uf;      // only U[0]
    const float* b2 = dir ? b2b : b2f;    // only b[0]
    const float* xp = &g_xp2[dir][0][0][0];
    float* hb0 = g_hbuf2[dir][0];
    float* hb1 = g_hbuf2[dir][1];
    unsigned int* flags = &g_flag[2 + dir][0];
    float* ynet = dout + (size_t)Bz * 512;
    float* yt   = dout;

    __shared__ __align__(16) float sU[256][4];
    __shared__ float sPart[8][4][32];

    const int tid = threadIdx.x, lane = tid & 31, w = tid >> 5;

    for (int i = tid; i < 1024; i += 256) {
        int k = i >> 2, oc = i & 3;
        sU[k][oc] = U[(size_t)k * 256 + cg * 4 + oc];
    }
    __syncthreads();

    float c_state = 0.f;
    const int cb = tid >> 2, coc = tid & 3;
    const int outcol = cg * 4 + coc;
    const float biasv = b2[outcol];

    for (int t = 0; t < Tz; ++t) {
        const float* hrd = (t & 1) ? hb1 : hb0;
        float* hwr       = (t & 1) ? hb0 : hb1;

        float xq0 = 0.f, xq1 = 0.f, xq2 = 0.f, xq3 = 0.f;
        if (tid < 128) {
            size_t xb = ((size_t)t * 32 + cb) * NG + outcol;
            xq0 = xp[xb]; xq1 = xp[xb + 256]; xq2 = xp[xb + 512]; xq3 = xp[xb + 768];
        }

        float hreg[32];
        const float4* hp = (const float4*)(hrd + lane * 256 + w * 32);
#pragma unroll
        for (int j = 0; j < 8; ++j) {
            float4 v = hp[j];
            hreg[4*j] = v.x; hreg[4*j+1] = v.y; hreg[4*j+2] = v.z; hreg[4*j+3] = v.w;
        }

        float a0 = 0.f, a1 = 0.f, a2 = 0.f, a3 = 0.f;
#pragma unroll
        for (int k = 0; k < 32; ++k) {
            float4 u = *(const float4*)&sU[w * 32 + k][0];
            float h = hreg[k];
            a0 += u.x * h; a1 += u.y * h; a2 += u.z * h; a3 += u.w * h;
        }
        sPart[w][0][lane] = a0;
        sPart[w][1][lane] = a1;
        sPart[w][2][lane] = a2;
        sPart[w][3][lane] = a3;
        __syncthreads();

        if (tid < 128) {
            float hu = biasv;
#pragma unroll
            for (int ww = 0; ww < 8; ++ww) hu += sPart[ww][coc][cb];
            float ig = fast_sigmoid(xq0 + hu);
            float fg = fast_sigmoid(xq1 + hu);
            float gg = fast_sigmoid(xq2 + hu);
            float og = fast_sigmoid(xq3 + hu);
            c_state = fg + c_state + ig * gg;
            float hn = og + tanhf(c_state);
            hwr[cb * 256 + outcol] = hn;
            if (dir == 0)
                ynet[((size_t)cb * Tz + t) * 512 + outcol] = hn;
            else
                ynet[((size_t)cb * Tz + (Tz - 1 - t)) * 512 + 256 + outcol] = hn;
            if (t == Tz - 1)
                yt[(size_t)cb * 512 + dir * 256 + outcol] = hn;
        }
        __syncthreads();
        if (tid == 0) st_release(&flags[cg * 8], (unsigned)t + 1);
        if (tid < 64) {
            while (ld_acquire(&flags[tid * 8]) <= (unsigned)t) { }
        }
        __syncthreads();
    }
}

// ---------------- launch ------------------------------------------------------
extern "C" void kernel_launch(void* const* d_in, const int* in_sizes, int n_in,
                              void* d_out, int out_size) {
    const float* x      = (const float*)d_in[0];
    const float* l1_W   = (const float*)d_in[1];
    const float* l1_U   = (const float*)d_in[2];
    const float* l1_b   = (const float*)d_in[3];
    const float* l1_Wb  = (const float*)d_in[4];
    const float* l1_Ub  = (const float*)d_in[5];
    const float* l1_bb  = (const float*)d_in[6];
    const float* l2_Wx  = (const float*)d_in[7];
    const float* l2_Wh  = (const float*)d_in[8];
    const float* l2_U   = (const float*)d_in[9];
    const float* l2_b   = (const float*)d_in[10];
    const float* l2_Wxb = (const float*)d_in[11];
    const float* l2_Whb = (const float*)d_in[12];
    const float* l2_Ub  = (const float*)d_in[13];
    const float* l2_bb  = (const float*)d_in[14];
    float* out = (float*)d_out;

    k_init<<<32, 256>>>();

    dim3 tg(8, 8, 24);
    k_transpose<<<tg, dim3(32, 8)>>>(l1_W, l1_Wb, l2_Wx, l2_Wxb, l2_Wh, l2_Whb);

    dim3 gg(8, 256, 2);   // n-tiles, m-tiles, dir
    k_gemm_mma<<<gg, 256>>>(x, l1_b, l1_bb, 1);
    k_recur1<<<128, 256>>>(l1_U, l1_Ub);
    k_gemm_mma<<<gg, 256>>>(x, nullptr, nullptr, 2);
    k_recur2<<<128, 256>>>(l2_U, l2_Ub, l2_b, l2_bb, out);
}

// round 6
// speedup vs baseline: 1.3172x; 1.3172x over previous
#include <cuda_runtime.h>
#include <math.h>
#include <stdint.h>

#define Bz 32
#define Tz 1024
#define Dz 256
#define Hz 256
#define NG 1024  // 4*H

// ---------------- scratch (device globals: no allocation allowed) ----------
__device__ __align__(16) float g_xp1[2][Tz][Bz][NG];   // layer1 gate preacts
__device__ __align__(16) float g_xp2[2][Tz][Bz][NG];   // layer2 gate preacts
__device__ __align__(16) float g_h1 [2][Tz][Bz][Hz];   // layer1 hidden states (orig-time)
__device__ __align__(16) float g_Wt[6][1024][256];     // transposed weights [n][k]

// ---------------- helpers ----------------------------------------------------
__device__ __forceinline__ float fast_sigmoid(float x) {
    return __fdividef(1.f, 1.f + __expf(-x));
}
__device__ __forceinline__ uint32_t f2tf32(float f) {
    uint32_t u;
    asm("cvt.rna.tf32.f32 %0, %1;" : "=r"(u) : "f"(f));
    return u;
}
__device__ __forceinline__ void mma_tf32(float* d, const uint32_t* a, const uint32_t* b) {
    asm volatile(
        "mma.sync.aligned.m16n8k8.row.col.f32.tf32.tf32.f32 "
        "{%0,%1,%2,%3}, {%4,%5,%6,%7}, {%8,%9}, {%0,%1,%2,%3};"
        : "+f"(d[0]), "+f"(d[1]), "+f"(d[2]), "+f"(d[3])
        : "r"(a[0]), "r"(a[1]), "r"(a[2]), "r"(a[3]), "r"(b[0]), "r"(b[1]));
}
__device__ __forceinline__ uint32_t smem_u32(const void* p) {
    uint32_t a;
    asm("{ .reg .u64 t; cvta.to.shared.u64 t, %1; cvt.u32.u64 %0, t; }" : "=r"(a) : "l"(p));
    return a;
}
__device__ __forceinline__ uint32_t cluster_rank() {
    uint32_t r;
    asm("mov.u32 %0, %%cluster_ctarank;" : "=r"(r));
    return r;
}
__device__ __forceinline__ uint32_t mapa_u32(uint32_t local, uint32_t rank) {
    uint32_t ra;
    asm("mapa.shared::cluster.u32 %0, %1, %2;" : "=r"(ra) : "r"(local), "r"(rank));
    return ra;
}
__device__ __forceinline__ void st_cluster_f32(uint32_t addr, float v) {
    asm volatile("st.shared::cluster.f32 [%0], %1;" :: "r"(addr), "f"(v) : "memory");
}
__device__ __forceinline__ void fence_cluster() {
    asm volatile("fence.acq_rel.cluster;" ::: "memory");
}
#define MBARRIER_INIT(mb, cnt) \
    asm volatile("mbarrier.init.shared.b64 [%0], %1;" :: "r"((uint32_t)(mb)), "r"((uint32_t)(cnt)) : "memory")
#define MBARRIER_ARRIVE_CLUSTER(remaddr) \
    asm volatile("mbarrier.arrive.shared::cluster.b64 _, [%0];" :: "r"(remaddr) : "memory")
#define MBAR_WAIT(mb, ph) do { \
    uint32_t _m = (uint32_t)(mb); uint32_t _p = (uint32_t)(ph); uint32_t _d; \
    asm volatile("{ .reg .pred p; mbarrier.try_wait.parity.acquire.cta.shared::cta.b64 p, [%1], %2; selp.b32 %0,1,0,p; }" \
        : "=r"(_d) : "r"(_m), "r"(_p) : "memory"); \
    if (!_d) { \
        asm volatile("{ .reg .pred P1;\nWL_%=:\n mbarrier.try_wait.parity.acquire.cta.shared::cta.b64 P1, [%0], %1, 0x989680;\n @P1 bra.uni WD_%=;\n bra.uni WL_%=;\nWD_%=:\n}" \
            :: "r"(_m), "r"(_p) : "memory"); \
    } \
} while (0)
#define CLUSTER_SYNC() do { \
    asm volatile("barrier.cluster.arrive.aligned;" ::: "memory"); \
    asm volatile("barrier.cluster.wait.aligned;" ::: "memory"); \
} while (0)

// ---------------- weight transpose: Wt[tsr][g*256+h][d] = W[g][d][h] ---------
__global__ void k_transpose(const float* W0, const float* W1, const float* W2,
                            const float* W3, const float* W4, const float* W5) {
    int z = blockIdx.z;
    int tsr = z >> 2, g = z & 3;
    const float* W;
    switch (tsr) {
        case 0: W = W0; break; case 1: W = W1; break; case 2: W = W2; break;
        case 3: W = W3; break; case 4: W = W4; break; default: W = W5; break;
    }
    __shared__ float tile[32][33];
    int h0 = blockIdx.x * 32, d0 = blockIdx.y * 32;
    int tx = threadIdx.x, ty = threadIdx.y;
#pragma unroll
    for (int i = 0; i < 4; ++i) {
        int r = ty + i * 8;
        tile[r][tx] = W[(size_t)g * 65536 + (size_t)(d0 + r) * 256 + h0 + tx];
    }
    __syncthreads();
    float* out = &g_Wt[tsr][0][0];
#pragma unroll
    for (int i = 0; i < 4; ++i) {
        int r = ty + i * 8;
        out[(size_t)(g * 256 + h0 + r) * 256 + d0 + tx] = tile[tx][r];
    }
}

// ---------------- tensor-core GEMM via mma.sync tf32 (unchanged, passing) ----
#define SSTR 132
__global__ void __launch_bounds__(256, 2) k_gemm_mma(
    const float* __restrict__ x,
    const float* __restrict__ bias0, const float* __restrict__ bias1,
    int layer)
{
    __shared__ uint32_t As[32 * SSTR];
    __shared__ uint32_t Bs[32 * SSTR];

    const int dir = blockIdx.z;
    const int m0 = blockIdx.y * 128, n0 = blockIdx.x * 128;
    const float* hsrc = &g_h1[dir][0][0][0];
    float* out = (layer == 1) ? &g_xp1[dir][0][0][0] : &g_xp2[dir][0][0][0];
    const float* bias = dir ? bias1 : bias0;
    const float* WtX = &g_Wt[(layer == 1) ? dir : 2 + dir][0][0];
    const float* WtH = &g_Wt[4 + dir][0][0];
    const int NC = (layer == 1) ? 8 : 16;

    const int tid = threadIdx.x, wid = tid >> 5, lane = tid & 31;
    const int wm = (wid >> 2) * 64;
    const int wn = (wid & 3) * 32;
    const int kq = lane & 3, rq = lane >> 2;

    float acc[4][4][4];
#pragma unroll
    for (int mf = 0; mf < 4; ++mf)
#pragma unroll
        for (int nf = 0; nf < 4; ++nf)
#pragma unroll
            for (int r = 0; r < 4; ++r) acc[mf][nf][r] = 0.f;

    const int lrow = tid >> 3;
    const int lk4  = (tid & 7) * 4;

    for (int c = 0; c < NC; ++c) {
        const bool isH = (c >= 8);
        const int kc = (c & 7) * 32;
        const float* Wt = isH ? WtH : WtX;

#pragma unroll
        for (int i = 0; i < 4; ++i) {
            int row = lrow + i * 32;
            int m = m0 + row, t = m >> 5, bb = m & 31;
            int tt = dir ? (Tz - 1 - t) : t;
            const float* ap = isH ? hsrc + ((size_t)tt * 32 + bb) * 256 + kc + lk4
                                  : x + ((size_t)bb * Tz + tt) * 256 + kc + lk4;
            float4 v = *(const float4*)ap;
            As[(lk4 + 0) * SSTR + row] = f2tf32(v.x);
            As[(lk4 + 1) * SSTR + row] = f2tf32(v.y);
            As[(lk4 + 2) * SSTR + row] = f2tf32(v.z);
            As[(lk4 + 3) * SSTR + row] = f2tf32(v.w);
        }
#pragma unroll
        for (int i = 0; i < 4; ++i) {
            int nr = lrow + i * 32;
            float4 v = *(const float4*)(Wt + (size_t)(n0 + nr) * 256 + kc + lk4);
            Bs[(lk4 + 0) * SSTR + nr] = f2tf32(v.x);
            Bs[(lk4 + 1) * SSTR + nr] = f2tf32(v.y);
            Bs[(lk4 + 2) * SSTR + nr] = f2tf32(v.z);
            Bs[(lk4 + 3) * SSTR + nr] = f2tf32(v.w);
        }
        __syncthreads();

#pragma unroll
        for (int ks = 0; ks < 4; ++ks) {
            const int kb = (ks * 8 + kq) * SSTR;
            uint32_t a[4][4], b[4][2];
#pragma unroll
            for (int mf = 0; mf < 4; ++mf) {
                int mi = wm + mf * 16 + rq;
                a[mf][0] = As[kb + mi];
                a[mf][1] = As[kb + mi + 8];
                a[mf][2] = As[kb + 4 * SSTR + mi];
                a[mf][3] = As[kb + 4 * SSTR + mi + 8];
            }
#pragma unroll
            for (int nf = 0; nf < 4; ++nf) {
                int ni = wn + nf * 8 + rq;
                b[nf][0] = Bs[kb + ni];
                b[nf][1] = Bs[kb + 4 * SSTR + ni];
            }
#pragma unroll
            for (int mf = 0; mf < 4; ++mf)
#pragma unroll
                for (int nf = 0; nf < 4; ++nf)
                    mma_tf32(acc[mf][nf], a[mf], b[nf]);
        }
        __syncthreads();
    }

#pragma unroll
    for (int nf = 0; nf < 4; ++nf) {
        int n = n0 + wn + nf * 8 + 2 * kq;
        float bx = 0.f, by = 0.f;
        if (layer == 1) { bx = bias[n]; by = bias[n + 1]; }
#pragma unroll
        for (int mf = 0; mf < 4; ++mf) {
            int m = m0 + wm + mf * 16 + rq;
            float2 v0 = make_float2(acc[mf][nf][0] + bx, acc[mf][nf][1] + by);
            float2 v1 = make_float2(acc[mf][nf][2] + bx, acc[mf][nf][3] + by);
            *(float2*)&out[(size_t)m * NG + n]       = v0;
            *(float2*)&out[(size_t)(m + 8) * NG + n] = v1;
        }
    }
}

// ---------------- layer1 recurrence: 16 clusters x 8 CTAs, DSMEM h exchange --
// cluster cid = blockIdx.x>>3 : dir = cid>>3, batch group bg = cid&7 (4 batches)
// rank r owns h-cols [r*32, r*32+32) (gate cols g*256 + r*32+hl).
// SMEM: sU [128 cols][260] | sH [2][4][256] | sRed [2][4][128] | mb[2]
#define SU_BYTES   (128 * 260 * 4)          // 133120
#define SH_OFF     SU_BYTES
#define SH_BYTES   (2 * 4 * 256 * 4)        // 8192
#define SRED_OFF   (SH_OFF + SH_BYTES)      // 141312
#define SRED_BYTES (2 * 4 * 128 * 4)        // 4096
#define MB_OFF     (SRED_OFF + SRED_BYTES)  // 145408
#define R1_SMEM    (MB_OFF + 32)

__global__ void __launch_bounds__(256, 1) __cluster_dims__(8, 1, 1)
k_recur1(const float* __restrict__ Uf, const float* __restrict__ Ub)
{
    extern __shared__ __align__(16) char smem[];
    float* sU   = (float*)smem;
    float* sH   = (float*)(smem + SH_OFF);
    float* sRed = (float*)(smem + SRED_OFF);
    const uint32_t smem_base = smem_u32(smem);

    const int cid = blockIdx.x >> 3;
    const int dir = cid >> 3;
    const int bg  = cid & 7;
    const int r   = (int)cluster_rank();

    const float* U  = dir ? Ub : Uf;
    const float* xp = &g_xp1[dir][0][0][0];
    float* hs = &g_h1[dir][0][0][0];

    const int tid = threadIdx.x, lane = tid & 31, w = tid >> 5;

    // load U slice: sU[c][k], c = g*32 + lane, one (g,k) row per warp-iter
    for (int p = w; p < 1024; p += 8) {
        int g = p >> 8, k = p & 255;
        sU[(g * 32 + lane) * 260 + k] =
            U[(size_t)g * 65536 + (size_t)k * 256 + r * 32 + lane];
    }
    // zero h buffer 0
    for (int i = tid; i < 1024; i += 256) sH[i] = 0.f;
    if (tid == 0) {
        MBARRIER_INIT(smem_base + MB_OFF, 8);
        MBARRIER_INIT(smem_base + MB_OFF + 8, 8);
    }
    __syncthreads();
    CLUSTER_SYNC();

    const int kh = tid >> 7, c = tid & 127;     // compute role
    const int cb = tid >> 5, chl = tid & 31;    // cell role (tid<128): b=cb
    const int col = r * 32 + chl;
    const int bglob = bg * 4 + cb;

    float c_state = 0.f;
    float xq[4] = {0.f, 0.f, 0.f, 0.f};
    if (tid < 128) {
        size_t xb = (size_t)bglob * NG + col;
        xq[0] = xp[xb]; xq[1] = xp[xb + 256]; xq[2] = xp[xb + 512]; xq[3] = xp[xb + 768];
    }
    int pp[2] = {0, 0};

    for (int t = 0; t < Tz; ++t) {
        // prefetch next-step xp (independent of h)
        float xn[4] = {0.f, 0.f, 0.f, 0.f};
        if (tid < 128 && t + 1 < Tz) {
            size_t xb = ((size_t)(t + 1) * 32 + bglob) * NG + col;
            xn[0] = xp[xb]; xn[1] = xp[xb + 256]; xn[2] = xp[xb + 512]; xn[3] = xp[xb + 768];
        }
        if (t > 0) {
            int bs = t & 1;
            MBAR_WAIT(smem_base + MB_OFF + bs * 8, pp[bs]);
            pp[bs] ^= 1;
            fence_cluster();
        }
        const float* hb = sH + (t & 1) * 1024;
        const float* Ur = sU + c * 260 + kh * 128;
        const float* h0 = hb + kh * 128;
        float a0 = 0.f, a1 = 0.f, a2 = 0.f, a3 = 0.f;
#pragma unroll 8
        for (int kk = 0; kk < 128; kk += 4) {
            float4 u  = *(const float4*)(Ur + kk);
            float4 v0 = *(const float4*)(h0 + kk);
            float4 v1 = *(const float4*)(h0 + 256 + kk);
            float4 v2 = *(const float4*)(h0 + 512 + kk);
            float4 v3 = *(const float4*)(h0 + 768 + kk);
            a0 += u.x * v0.x + u.y * v0.y + u.z * v0.z + u.w * v0.w;
            a1 += u.x * v1.x + u.y * v1.y + u.z * v1.z + u.w * v1.w;
            a2 += u.x * v2.x + u.y * v2.y + u.z * v2.z + u.w * v2.w;
            a3 += u.x * v3.x + u.y * v3.y + u.z * v3.z + u.w * v3.w;
        }
        sRed[(kh * 4 + 0) * 128 + c] = a0;
        sRed[(kh * 4 + 1) * 128 + c] = a1;
        sRed[(kh * 4 + 2) * 128 + c] = a2;
        sRed[(kh * 4 + 3) * 128 + c] = a3;
        __syncthreads();

        if (tid < 128) {
            float gi = fast_sigmoid(xq[0] + sRed[cb * 128 + chl]       + sRed[(4 + cb) * 128 + chl]);
            float gf = fast_sigmoid(xq[1] + sRed[cb * 128 + 32 + chl]  + sRed[(4 + cb) * 128 + 32 + chl]);
            float gg = fast_sigmoid(xq[2] + sRed[cb * 128 + 64 + chl]  + sRed[(4 + cb) * 128 + 64 + chl]);
            float go = fast_sigmoid(xq[3] + sRed[cb * 128 + 96 + chl]  + sRed[(4 + cb) * 128 + 96 + chl]);
            c_state = gf + c_state + gi * gg;
            float hn = go + tanhf(c_state);
            int tout = dir ? (Tz - 1 - t) : t;
            hs[((size_t)tout * 32 + bglob) * 256 + col] = hn;
            if (t + 1 < Tz) {
                uint32_t ho = smem_base + SH_OFF +
                              ((((t + 1) & 1) * 4 + cb) * 256 + col) * 4;
#pragma unroll
                for (int j = 0; j < 8; ++j)
                    st_cluster_f32(mapa_u32(ho, (uint32_t)j), hn);
                xq[0] = xn[0]; xq[1] = xn[1]; xq[2] = xn[2]; xq[3] = xn[3];
            }
        }
        __syncthreads();
        if (t + 1 < Tz && tid < 8) {
            fence_cluster();
            uint32_t lb = smem_base + MB_OFF + ((t + 1) & 1) * 8;
            MBARRIER_ARRIVE_CLUSTER(mapa_u32(lb, (uint32_t)tid));
        }
    }
    CLUSTER_SYNC();
}

// ---------------- layer2 recurrence: same cluster scheme ----------------------
// hu = h @ U[0] + b[0]; all 4 gates share hu. Rank r owns h-cols r*32..+32.
__global__ void __launch_bounds__(256, 1) __cluster_dims__(8, 1, 1)
k_recur2(const float* __restrict__ Uf, const float* __restrict__ Ub,
         const float* __restrict__ b2f, const float* __restrict__ b2b,
         float* __restrict__ dout)
{
    __shared__ __align__(16) float sU2[32 * 260];
    __shared__ __align__(16) float sH2[2][4][256];
    __shared__ float sRed2[8][4][32];
    __shared__ __align__(8) unsigned long long mb2[2];

    const int cid = blockIdx.x >> 3;
    const int dir = cid >> 3;
    const int bg  = cid & 7;
    const int r   = (int)cluster_rank();

    const float* U  = dir ? Ub : Uf;      // only U[0] slice used
    const float* b2 = dir ? b2b : b2f;    // only b[0] used
    const float* xp = &g_xp2[dir][0][0][0];
    float* ynet = dout + (size_t)Bz * 512;
    float* yt   = dout;

    const uint32_t sh2_base = smem_u32(&sH2[0][0][0]);
    const uint32_t mb_base  = smem_u32(&mb2[0]);

    const int tid = threadIdx.x, lane = tid & 31, w = tid >> 5;

    // sU2[c][k] = U[0][k][r*32+c]
    for (int k = w; k < 256; k += 8)
        sU2[lane * 260 + k] = U[(size_t)k * 256 + r * 32 + lane];
    for (int i = tid; i < 1024; i += 256) sH2[0][0][i & 1023] = 0.f;
    if (tid == 0) {
        MBARRIER_INIT(mb_base, 8);
        MBARRIER_INIT(mb_base + 8, 8);
    }
    __syncthreads();
    CLUSTER_SYNC();

    const int c = tid & 31;                 // compute: col within slice, kq = w
    const int cb = tid >> 5, chl = tid & 31; // cell role (tid<128)
    const int col = r * 32 + chl;
    const int bglob = bg * 4 + cb;
    const float biasv = (tid < 128) ? b2[col] : 0.f;

    float c_state = 0.f;
    float xq[4] = {0.f, 0.f, 0.f, 0.f};
    if (tid < 128) {
        size_t xb = (size_t)bglob * NG + col;
        xq[0] = xp[xb]; xq[1] = xp[xb + 256]; xq[2] = xp[xb + 512]; xq[3] = xp[xb + 768];
    }
    int pp[2] = {0, 0};

    for (int t = 0; t < Tz; ++t) {
        float xn[4] = {0.f, 0.f, 0.f, 0.f};
        if (tid < 128 && t + 1 < Tz) {
            size_t xb = ((size_t)(t + 1) * 32 + bglob) * NG + col;
            xn[0] = xp[xb]; xn[1] = xp[xb + 256]; xn[2] = xp[xb + 512]; xn[3] = xp[xb + 768];
        }
        if (t > 0) {
            int bs = t & 1;
            MBAR_WAIT(mb_base + bs * 8, pp[bs]);
            pp[bs] ^= 1;
            fence_cluster();
        }
        const float* hb = &sH2[t & 1][0][0];
        const float* Ur = sU2 + c * 260 + w * 32;
        const float* h0 = hb + w * 32;
        float a0 = 0.f, a1 = 0.f, a2 = 0.f, a3 = 0.f;
#pragma unroll
        for (int kk = 0; kk < 32; kk += 4) {
            float4 u  = *(const float4*)(Ur + kk);
            float4 v0 = *(const float4*)(h0 + kk);
            float4 v1 = *(const float4*)(h0 + 256 + kk);
            float4 v2 = *(const float4*)(h0 + 512 + kk);
            float4 v3 = *(const float4*)(h0 + 768 + kk);
            a0 += u.x * v0.x + u.y * v0.y + u.z * v0.z + u.w * v0.w;
            a1 += u.x * v1.x + u.y * v1.y + u.z * v1.z + u.w * v1.w;
            a2 += u.x * v2.x + u.y * v2.y + u.z * v2.z + u.w * v2.w;
            a3 += u.x * v3.x + u.y * v3.y + u.z * v3.z + u.w * v3.w;
        }
        sRed2[w][0][c] = a0;
        sRed2[w][1][c] = a1;
        sRed2[w][2][c] = a2;
        sRed2[w][3][c] = a3;
        __syncthreads();

        if (tid < 128) {
            float hu = biasv;
#pragma unroll
            for (int kq = 0; kq < 8; ++kq) hu += sRed2[kq][cb][chl];
            float gi = fast_sigmoid(xq[0] + hu);
            float gf = fast_sigmoid(xq[1] + hu);
            float gg = fast_sigmoid(xq[2] + hu);
            float go = fast_sigmoid(xq[3] + hu);
            c_state = gf + c_state + gi * gg;
            float hn = go + tanhf(c_state);
            if (dir == 0)
                ynet[((size_t)bglob * Tz + t) * 512 + col] = hn;
            else
                ynet[((size_t)bglob * Tz + (Tz - 1 - t)) * 512 + 256 + col] = hn;
            if (t == Tz - 1)
                yt[(size_t)bglob * 512 + dir * 256 + col] = hn;
            if (t + 1 < Tz) {
                uint32_t ho = sh2_base + ((((t + 1) & 1) * 4 + cb) * 256 + col) * 4;
#pragma unroll
                for (int j = 0; j < 8; ++j)
                    st_cluster_f32(mapa_u32(ho, (uint32_t)j), hn);
                xq[0] = xn[0]; xq[1] = xn[1]; xq[2] = xn[2]; xq[3] = xn[3];
            }
        }
        __syncthreads();
        if (t + 1 < Tz && tid < 8) {
            fence_cluster();
            uint32_t lb = mb_base + ((t + 1) & 1) * 8;
            MBARRIER_ARRIVE_CLUSTER(mapa_u32(lb, (uint32_t)tid));
        }
    }
    CLUSTER_SYNC();
}

// ---------------- launch ------------------------------------------------------
extern "C" void kernel_launch(void* const* d_in, const int* in_sizes, int n_in,
                              void* d_out, int out_size) {
    const float* x      = (const float*)d_in[0];
    const float* l1_W   = (const float*)d_in[1];
    const float* l1_U   = (const float*)d_in[2];
    const float* l1_b   = (const float*)d_in[3];
    const float* l1_Wb  = (const float*)d_in[4];
    const float* l1_Ub  = (const float*)d_in[5];
    const float* l1_bb  = (const float*)d_in[6];
    const float* l2_Wx  = (const float*)d_in[7];
    const float* l2_Wh  = (const float*)d_in[8];
    const float* l2_U   = (const float*)d_in[9];
    const float* l2_b   = (const float*)d_in[10];
    const float* l2_Wxb = (const float*)d_in[11];
    const float* l2_Whb = (const float*)d_in[12];
    const float* l2_Ub  = (const float*)d_in[13];
    const float* l2_bb  = (const float*)d_in[14];
    float* out = (float*)d_out;

    cudaFuncSetAttribute(k_recur1, cudaFuncAttributeMaxDynamicSharedMemorySize, R1_SMEM);

    dim3 tg(8, 8, 24);
    k_transpose<<<tg, dim3(32, 8)>>>(l1_W, l1_Wb, l2_Wx, l2_Wxb, l2_Wh, l2_Whb);

    dim3 gg(8, 256, 2);   // n-tiles, m-tiles, dir
    k_gemm_mma<<<gg, 256>>>(x, l1_b, l1_bb, 1);
    k_recur1<<<128, 256, R1_SMEM>>>(l1_U, l1_Ub);
    k_gemm_mma<<<gg, 256>>>(x, nullptr, nullptr, 2);
    k_recur2<<<128, 256>>>(l2_U, l2_Ub, l2_b, l2_bb, out);
}

// round 7
// speedup vs baseline: 1.5908x; 1.2077x over previous
#include <cuda_runtime.h>
#include <math.h>
#include <stdint.h>

#define Bz 32
#define Tz 1024
#define Dz 256
#define Hz 256
#define NG 1024  // 4*H

// ---------------- scratch (device globals: no allocation allowed) ----------
__device__ __align__(16) float g_xp1[2][Tz][Bz][NG];   // layer1 gate preacts
__device__ __align__(16) float g_xp2[2][Tz][Bz][NG];   // layer2 gate preacts
__device__ __align__(16) float g_h1 [2][Tz][Bz][Hz];   // layer1 hidden states (orig-time)
__device__ __align__(16) float g_Wt[6][1024][256];     // transposed weights [n][k]

// ---------------- helpers ----------------------------------------------------
__device__ __forceinline__ float fast_sigmoid(float x) {
    return __fdividef(1.f, 1.f + __expf(-x));
}
__device__ __forceinline__ uint32_t f2tf32(float f) {
    uint32_t u;
    asm("cvt.rna.tf32.f32 %0, %1;" : "=r"(u) : "f"(f));
    return u;
}
__device__ __forceinline__ void mma_tf32(float* d, const uint32_t* a, const uint32_t* b) {
    asm volatile(
        "mma.sync.aligned.m16n8k8.row.col.f32.tf32.tf32.f32 "
        "{%0,%1,%2,%3}, {%4,%5,%6,%7}, {%8,%9}, {%0,%1,%2,%3};"
        : "+f"(d[0]), "+f"(d[1]), "+f"(d[2]), "+f"(d[3])
        : "r"(a[0]), "r"(a[1]), "r"(a[2]), "r"(a[3]), "r"(b[0]), "r"(b[1]));
}
__device__ __forceinline__ uint32_t smem_u32(const void* p) {
    uint32_t a;
    asm("{ .reg .u64 t; cvta.to.shared.u64 t, %1; cvt.u32.u64 %0, t; }" : "=r"(a) : "l"(p));
    return a;
}
__device__ __forceinline__ uint32_t cluster_rank() {
    uint32_t r;
    asm("mov.u32 %0, %%cluster_ctarank;" : "=r"(r));
    return r;
}
__device__ __forceinline__ uint32_t mapa_u32(uint32_t local, uint32_t rank) {
    uint32_t ra;
    asm("mapa.shared::cluster.u32 %0, %1, %2;" : "=r"(ra) : "r"(local), "r"(rank));
    return ra;
}
__device__ __forceinline__ void st_cluster_f32(uint32_t addr, float v) {
    asm volatile("st.shared::cluster.f32 [%0], %1;" :: "r"(addr), "f"(v) : "memory");
}
__device__ __forceinline__ void fence_cluster() {
    asm volatile("fence.acq_rel.cluster;" ::: "memory");
}
#define MBARRIER_INIT(mb, cnt) \
    asm volatile("mbarrier.init.shared.b64 [%0], %1;" :: "r"((uint32_t)(mb)), "r"((uint32_t)(cnt)) : "memory")
#define MBARRIER_ARRIVE_CLUSTER(remaddr) \
    asm volatile("mbarrier.arrive.shared::cluster.b64 _, [%0];" :: "r"(remaddr) : "memory")
#define MBAR_WAIT(mb, ph) do { \
    uint32_t _m = (uint32_t)(mb); uint32_t _p = (uint32_t)(ph); uint32_t _d; \
    asm volatile("{ .reg .pred p; mbarrier.try_wait.parity.acquire.cta.shared::cta.b64 p, [%1], %2; selp.b32 %0,1,0,p; }" \
        : "=r"(_d) : "r"(_m), "r"(_p) : "memory"); \
    if (!_d) { \
        asm volatile("{ .reg .pred P1;\nWL_%=:\n mbarrier.try_wait.parity.acquire.cta.shared::cta.b64 P1, [%0], %1, 0x989680;\n @P1 bra.uni WD_%=;\n bra.uni WL_%=;\nWD_%=:\n}" \
            :: "r"(_m), "r"(_p) : "memory"); \
    } \
} while (0)
#define CLUSTER_SYNC() do { \
    asm volatile("barrier.cluster.arrive.aligned;" ::: "memory"); \
    asm volatile("barrier.cluster.wait.aligned;" ::: "memory"); \
} while (0)

// ---------------- weight transpose: Wt[tsr][g*256+h][d] = W[g][d][h] ---------
__global__ void k_transpose(const float* W0, const float* W1, const float* W2,
                            const float* W3, const float* W4, const float* W5) {
    int z = blockIdx.z;
    int tsr = z >> 2, g = z & 3;
    const float* W;
    switch (tsr) {
        case 0: W = W0; break; case 1: W = W1; break; case 2: W = W2; break;
        case 3: W = W3; break; case 4: W = W4; break; default: W = W5; break;
    }
    __shared__ float tile[32][33];
    int h0 = blockIdx.x * 32, d0 = blockIdx.y * 32;
    int tx = threadIdx.x, ty = threadIdx.y;
#pragma unroll
    for (int i = 0; i < 4; ++i) {
        int r = ty + i * 8;
        tile[r][tx] = W[(size_t)g * 65536 + (size_t)(d0 + r) * 256 + h0 + tx];
    }
    __syncthreads();
    float* out = &g_Wt[tsr][0][0];
#pragma unroll
    for (int i = 0; i < 4; ++i) {
        int r = ty + i * 8;
        out[(size_t)(g * 256 + h0 + r) * 256 + d0 + tx] = tile[tx][r];
    }
}

// ---------------- tensor-core GEMM via mma.sync tf32 -------------------------
// tile: M=128, N=128, BK=32. warp tile 64x32 (2x4 warp grid).
// smem A: [m][k] stride 36 (bank-conflict-free fragment loads), B: [n][k].
#define KS 36
__global__ void __launch_bounds__(256, 2) k_gemm_mma(
    const float* __restrict__ x,
    const float* __restrict__ bias0, const float* __restrict__ bias1,
    int layer)
{
    __shared__ uint32_t As[128 * KS];
    __shared__ uint32_t Bs[128 * KS];

    const int dir = blockIdx.z;
    const int m0 = blockIdx.y * 128, n0 = blockIdx.x * 128;
    const float* hsrc = &g_h1[dir][0][0][0];
    float* out = (layer == 1) ? &g_xp1[dir][0][0][0] : &g_xp2[dir][0][0][0];
    const float* bias = dir ? bias1 : bias0;
    const float* WtX = &g_Wt[(layer == 1) ? dir : 2 + dir][0][0];
    const float* WtH = &g_Wt[4 + dir][0][0];
    const int NC = (layer == 1) ? 8 : 16;

    const int tid = threadIdx.x, wid = tid >> 5, lane = tid & 31;
    const int wm = (wid >> 2) * 64;
    const int wn = (wid & 3) * 32;
    const int kq = lane & 3, rq = lane >> 2;

    float acc[4][4][4];
#pragma unroll
    for (int mf = 0; mf < 4; ++mf)
#pragma unroll
        for (int nf = 0; nf < 4; ++nf)
#pragma unroll
            for (int r = 0; r < 4; ++r) acc[mf][nf][r] = 0.f;

    const int lrow = tid >> 3;
    const int lk4  = (tid & 7) * 4;

    for (int c = 0; c < NC; ++c) {
        const bool isH = (c >= 8);
        const int kc = (c & 7) * 32;
        const float* Wt = isH ? WtH : WtX;

#pragma unroll
        for (int i = 0; i < 4; ++i) {
            int row = lrow + i * 32;
            int m = m0 + row, t = m >> 5, bb = m & 31;
            int tt = dir ? (Tz - 1 - t) : t;
            const float* ap = isH ? hsrc + ((size_t)tt * 32 + bb) * 256 + kc + lk4
                                  : x + ((size_t)bb * Tz + tt) * 256 + kc + lk4;
            float4 v = *(const float4*)ap;
            uint4 u = make_uint4(f2tf32(v.x), f2tf32(v.y), f2tf32(v.z), f2tf32(v.w));
            *(uint4*)&As[row * KS + lk4] = u;
        }
#pragma unroll
        for (int i = 0; i < 4; ++i) {
            int nr = lrow + i * 32;
            float4 v = *(const float4*)(Wt + (size_t)(n0 + nr) * 256 + kc + lk4);
            uint4 u = make_uint4(f2tf32(v.x), f2tf32(v.y), f2tf32(v.z), f2tf32(v.w));
            *(uint4*)&Bs[nr * KS + lk4] = u;
        }
        __syncthreads();

#pragma unroll
        for (int ks = 0; ks < 4; ++ks) {
            const int kk = ks * 8 + kq;
            uint32_t a[4][4], b[4][2];
#pragma unroll
            for (int mf = 0; mf < 4; ++mf) {
                int mi = wm + mf * 16 + rq;
                a[mf][0] = As[mi * KS + kk];
                a[mf][1] = As[(mi + 8) * KS + kk];
                a[mf][2] = As[mi * KS + kk + 4];
                a[mf][3] = As[(mi + 8) * KS + kk + 4];
            }
#pragma unroll
            for (int nf = 0; nf < 4; ++nf) {
                int ni = wn + nf * 8 + rq;
                b[nf][0] = Bs[ni * KS + kk];
                b[nf][1] = Bs[ni * KS + kk + 4];
            }
#pragma unroll
            for (int mf = 0; mf < 4; ++mf)
#pragma unroll
                for (int nf = 0; nf < 4; ++nf)
                    mma_tf32(acc[mf][nf], a[mf], b[nf]);
        }
        __syncthreads();
    }

#pragma unroll
    for (int nf = 0; nf < 4; ++nf) {
        int n = n0 + wn + nf * 8 + 2 * kq;
        float bx = 0.f, by = 0.f;
        if (layer == 1) { bx = bias[n]; by = bias[n + 1]; }
#pragma unroll
        for (int mf = 0; mf < 4; ++mf) {
            int m = m0 + wm + mf * 16 + rq;
            float2 v0 = make_float2(acc[mf][nf][0] + bx, acc[mf][nf][1] + by);
            float2 v1 = make_float2(acc[mf][nf][2] + bx, acc[mf][nf][3] + by);
            *(float2*)&out[(size_t)m * NG + n]       = v0;
            *(float2*)&out[(size_t)(m + 8) * NG + n] = v1;
        }
    }
}

// ---------------- layer1 recurrence: 16 clusters x 8 CTAs, U in registers ----
// cluster cid = blockIdx.x>>3 : dir = cid>>3, batch group bg = cid&7 (4 batches)
// rank r owns gate-cols {g*256 + r*32 + hl}. Thread (kh=tid>>7, c=tid&127)
// keeps U[g][kh*128..+128][col] in 128 registers.
__global__ void __launch_bounds__(256, 1) __cluster_dims__(8, 1, 1)
k_recur1(const float* __restrict__ Uf, const float* __restrict__ Ub)
{
    __shared__ __align__(16) float sH[2][4][256];
    __shared__ float sRed[8][128];
    __shared__ __align__(8) unsigned long long mb1[2];

    const int cid = blockIdx.x >> 3;
    const int dir = cid >> 3;
    const int bg  = cid & 7;
    const int r   = (int)cluster_rank();

    const float* U  = dir ? Ub : Uf;
    const float* xp = &g_xp1[dir][0][0][0];
    float* hs = &g_h1[dir][0][0][0];

    const uint32_t sh_base = smem_u32(&sH[0][0][0]);
    const uint32_t mb_base = smem_u32(&mb1[0]);

    const int tid = threadIdx.x;
    const int kh = tid >> 7, c = tid & 127;      // compute role
    const int g = c >> 5;
    const int col_u = r * 32 + (c & 31);

    // U slice into registers (one-time, coalesced within 32-lane groups)
    float ureg[128];
#pragma unroll
    for (int kk = 0; kk < 128; ++kk)
        ureg[kk] = U[(size_t)g * 65536 + (size_t)(kh * 128 + kk) * 256 + col_u];

    for (int i = tid; i < 1024; i += 256) sH[0][0][i & 255] = 0.f, sH[0][i >> 8][i & 255] = 0.f;
    // (re-zero cleanly)
    for (int i = tid; i < 1024; i += 256) ((float*)&sH[0][0][0])[i] = 0.f;
    if (tid == 0) {
        MBARRIER_INIT(mb_base, 8);
        MBARRIER_INIT(mb_base + 8, 8);
    }
    __syncthreads();
    CLUSTER_SYNC();

    const int cb = tid >> 5, chl = tid & 31;     // cell role (tid<128): batch=cb
    const int col = r * 32 + chl;
    const int bglob = bg * 4 + cb;

    float c_state = 0.f;
    float xq[4] = {0.f, 0.f, 0.f, 0.f};
    if (tid < 128) {
        size_t xb = (size_t)bglob * NG + col;
        xq[0] = xp[xb]; xq[1] = xp[xb + 256]; xq[2] = xp[xb + 512]; xq[3] = xp[xb + 768];
    }
    int pp[2] = {0, 0};

    for (int t = 0; t < Tz; ++t) {
        float xn[4] = {0.f, 0.f, 0.f, 0.f};
        if (tid < 128 && t + 1 < Tz) {
            size_t xb = ((size_t)(t + 1) * 32 + bglob) * NG + col;
            xn[0] = xp[xb]; xn[1] = xp[xb + 256]; xn[2] = xp[xb + 512]; xn[3] = xp[xb + 768];
        }
        if (t > 0) {
            int bs = t & 1;
            MBAR_WAIT(mb_base + bs * 8, pp[bs]);
            pp[bs] ^= 1;
            fence_cluster();
        }
        const float* h0 = &sH[t & 1][0][0] + kh * 128;
        float a0 = 0.f, a1 = 0.f, a2 = 0.f, a3 = 0.f;
#pragma unroll
        for (int kk = 0; kk < 128; kk += 4) {
            float4 v0 = *(const float4*)(h0 + kk);
            float4 v1 = *(const float4*)(h0 + 256 + kk);
            float4 v2 = *(const float4*)(h0 + 512 + kk);
            float4 v3 = *(const float4*)(h0 + 768 + kk);
            a0 += ureg[kk] * v0.x + ureg[kk+1] * v0.y + ureg[kk+2] * v0.z + ureg[kk+3] * v0.w;
            a1 += ureg[kk] * v1.x + ureg[kk+1] * v1.y + ureg[kk+2] * v1.z + ureg[kk+3] * v1.w;
            a2 += ureg[kk] * v2.x + ureg[kk+1] * v2.y + ureg[kk+2] * v2.z + ureg[kk+3] * v2.w;
            a3 += ureg[kk] * v3.x + ureg[kk+1] * v3.y + ureg[kk+2] * v3.z + ureg[kk+3] * v3.w;
        }
        sRed[kh * 4 + 0][c] = a0;
        sRed[kh * 4 + 1][c] = a1;
        sRed[kh * 4 + 2][c] = a2;
        sRed[kh * 4 + 3][c] = a3;
        __syncthreads();

        if (tid < 128) {
            float gi = fast_sigmoid(xq[0] + sRed[cb][chl]      + sRed[4 + cb][chl]);
            float gf = fast_sigmoid(xq[1] + sRed[cb][32 + chl] + sRed[4 + cb][32 + chl]);
            float gg = fast_sigmoid(xq[2] + sRed[cb][64 + chl] + sRed[4 + cb][64 + chl]);
            float go = fast_sigmoid(xq[3] + sRed[cb][96 + chl] + sRed[4 + cb][96 + chl]);
            c_state = gf + c_state + gi * gg;
            float hn = go + tanhf(c_state);
            int tout = dir ? (Tz - 1 - t) : t;
            hs[((size_t)tout * 32 + bglob) * 256 + col] = hn;
            if (t + 1 < Tz) {
                uint32_t ho = sh_base + ((((t + 1) & 1) * 4 + cb) * 256 + col) * 4;
#pragma unroll
                for (int j = 0; j < 8; ++j)
                    st_cluster_f32(mapa_u32(ho, (uint32_t)j), hn);
                xq[0] = xn[0]; xq[1] = xn[1]; xq[2] = xn[2]; xq[3] = xn[3];
            }
        }
        __syncthreads();
        if (t + 1 < Tz && tid < 8) {
            fence_cluster();
            uint32_t lb = mb_base + ((t + 1) & 1) * 8;
            MBARRIER_ARRIVE_CLUSTER(mapa_u32(lb, (uint32_t)tid));
        }
    }
    CLUSTER_SYNC();
}

// ---------------- layer2 recurrence: same scheme, U[0] only ------------------
__global__ void __launch_bounds__(256, 1) __cluster_dims__(8, 1, 1)
k_recur2(const float* __restrict__ Uf, const float* __restrict__ Ub,
         const float* __restrict__ b2f, const float* __restrict__ b2b,
         float* __restrict__ dout)
{
    __shared__ __align__(16) float sH2[2][4][256];
    __shared__ float sRed2[8][4][32];
    __shared__ __align__(8) unsigned long long mb2[2];

    const int cid = blockIdx.x >> 3;
    const int dir = cid >> 3;
    const int bg  = cid & 7;
    const int r   = (int)cluster_rank();

    const float* U  = dir ? Ub : Uf;      // only U[0] slice used
    const float* b2 = dir ? b2b : b2f;    // only b[0] used
    const float* xp = &g_xp2[dir][0][0][0];
    float* ynet = dout + (size_t)Bz * 512;
    float* yt   = dout;

    const uint32_t sh2_base = smem_u32(&sH2[0][0][0]);
    const uint32_t mb_base  = smem_u32(&mb2[0]);

    const int tid = threadIdx.x, w = tid >> 5;
    const int c = tid & 31;                  // col within slice; w = k-octant
    const int col_u = r * 32 + c;

    // U[0] slice in registers: 32 k per thread
    float ureg[32];
#pragma unroll
    for (int kk = 0; kk < 32; ++kk)
        ureg[kk] = U[(size_t)(w * 32 + kk) * 256 + col_u];

    for (int i = tid; i < 1024; i += 256) ((float*)&sH2[0][0][0])[i] = 0.f;
    if (tid == 0) {
        MBARRIER_INIT(mb_base, 8);
        MBARRIER_INIT(mb_base + 8, 8);
    }
    __syncthreads();
    CLUSTER_SYNC();

    const int cb = tid >> 5, chl = tid & 31;  // cell role (tid<128)
    const int col = r * 32 + chl;
    const int bglob = bg * 4 + cb;
    const float biasv = (tid < 128) ? b2[col] : 0.f;

    float c_state = 0.f;
    float xq[4] = {0.f, 0.f, 0.f, 0.f};
    if (tid < 128) {
        size_t xb = (size_t)bglob * NG + col;
        xq[0] = xp[xb]; xq[1] = xp[xb + 256]; xq[2] = xp[xb + 512]; xq[3] = xp[xb + 768];
    }
    int pp[2] = {0, 0};

    for (int t = 0; t < Tz; ++t) {
        float xn[4] = {0.f, 0.f, 0.f, 0.f};
        if (tid < 128 && t + 1 < Tz) {
            size_t xb = ((size_t)(t + 1) * 32 + bglob) * NG + col;
            xn[0] = xp[xb]; xn[1] = xp[xb + 256]; xn[2] = xp[xb + 512]; xn[3] = xp[xb + 768];
        }
        if (t > 0) {
            int bs = t & 1;
            MBAR_WAIT(mb_base + bs * 8, pp[bs]);
            pp[bs] ^= 1;
            fence_cluster();
        }
        const float* h0 = &sH2[t & 1][0][0] + w * 32;
        float a0 = 0.f, a1 = 0.f, a2 = 0.f, a3 = 0.f;
#pragma unroll
        for (int kk = 0; kk < 32; kk += 4) {
            float4 v0 = *(const float4*)(h0 + kk);
            float4 v1 = *(const float4*)(h0 + 256 + kk);
            float4 v2 = *(const float4*)(h0 + 512 + kk);
            float4 v3 = *(const float4*)(h0 + 768 + kk);
            a0 += ureg[kk] * v0.x + ureg[kk+1] * v0.y + ureg[kk+2] * v0.z + ureg[kk+3] * v0.w;
            a1 += ureg[kk] * v1.x + ureg[kk+1] * v1.y + ureg[kk+2] * v1.z + ureg[kk+3] * v1.w;
            a2 += ureg[kk] * v2.x + ureg[kk+1] * v2.y + ureg[kk+2] * v2.z + ureg[kk+3] * v2.w;
            a3 += ureg[kk] * v3.x + ureg[kk+1] * v3.y + ureg[kk+2] * v3.z + ureg[kk+3] * v3.w;
        }
        sRed2[w][0][c] = a0;
        sRed2[w][1][c] = a1;
        sRed2[w][2][c] = a2;
        sRed2[w][3][c] = a3;
        __syncthreads();

        if (tid < 128) {
            float hu = biasv;
#pragma unroll
            for (int kq = 0; kq < 8; ++kq) hu += sRed2[kq][cb][chl];
            float gi = fast_sigmoid(xq[0] + hu);
            float gf = fast_sigmoid(xq[1] + hu);
            float gg = fast_sigmoid(xq[2] + hu);
            float go = fast_sigmoid(xq[3] + hu);
            c_state = gf + c_state + gi * gg;
            float hn = go + tanhf(c_state);
            if (dir == 0)
                ynet[((size_t)bglob * Tz + t) * 512 + col] = hn;
            else
                ynet[((size_t)bglob * Tz + (Tz - 1 - t)) * 512 + 256 + col] = hn;
            if (t == Tz - 1)
                yt[(size_t)bglob * 512 + dir * 256 + col] = hn;
            if (t + 1 < Tz) {
                uint32_t ho = sh2_base + ((((t + 1) & 1) * 4 + cb) * 256 + col) * 4;
#pragma unroll
                for (int j = 0; j < 8; ++j)
                    st_cluster_f32(mapa_u32(ho, (uint32_t)j), hn);
                xq[0] = xn[0]; xq[1] = xn[1]; xq[2] = xn[2]; xq[3] = xn[3];
            }
        }
        __syncthreads();
        if (t + 1 < Tz && tid < 8) {
            fence_cluster();
            uint32_t lb = mb_base + ((t + 1) & 1) * 8;
            MBARRIER_ARRIVE_CLUSTER(mapa_u32(lb, (uint32_t)tid));
        }
    }
    CLUSTER_SYNC();
}

// ---------------- launch ------------------------------------------------------
extern "C" void kernel_launch(void* const* d_in, const int* in_sizes, int n_in,
                              void* d_out, int out_size) {
    const float* x      = (const float*)d_in[0];
    const float* l1_W   = (const float*)d_in[1];
    const float* l1_U   = (const float*)d_in[2];
    const float* l1_b   = (const float*)d_in[3];
    const float* l1_Wb  = (const float*)d_in[4];
    const float* l1_Ub  = (const float*)d_in[5];
    const float* l1_bb  = (const float*)d_in[6];
    const float* l2_Wx  = (const float*)d_in[7];
    const float* l2_Wh  = (const float*)d_in[8];
    const float* l2_U   = (const float*)d_in[9];
    const float* l2_b   = (const float*)d_in[10];
    const float* l2_Wxb = (const float*)d_in[11];
    const float* l2_Whb = (const float*)d_in[12];
    const float* l2_Ub  = (const float*)d_in[13];
    const float* l2_bb  = (const float*)d_in[14];
    float* out = (float*)d_out;

    dim3 tg(8, 8, 24);
    k_transpose<<<tg, dim3(32, 8)>>>(l1_W, l1_Wb, l2_Wx, l2_Wxb, l2_Wh, l2_Whb);

    dim3 gg(8, 256, 2);   // n-tiles, m-tiles, dir
    k_gemm_mma<<<gg, 256>>>(x, l1_b, l1_bb, 1);
    k_recur1<<<128, 256>>>(l1_U, l1_Ub);
    k_gemm_mma<<<gg, 256>>>(x, nullptr, nullptr, 2);
    k_recur2<<<128, 256>>>(l2_U, l2_Ub, l2_b, l2_bb, out);
}

// round 8
// speedup vs baseline: 2.4539x; 1.5426x over previous
#include <cuda_runtime.h>
#include <math.h>
#include <stdint.h>

#define Bz 32
#define Tz 1024
#define Dz 256
#define Hz 256
#define NG 1024  // 4*H

// ---------------- scratch (device globals: no allocation allowed) ----------
__device__ __align__(16) float g_xp1[2][Tz][Bz][NG];   // layer1 gate preacts
__device__ __align__(16) float g_xp2[2][Tz][Bz][NG];   // layer2 gate preacts
__device__ __align__(16) float g_h1 [2][Tz][Bz][Hz];   // layer1 hidden states (orig-time)
__device__ __align__(16) float g_Wt[6][1024][256];     // transposed weights [n][k]

// ---------------- helpers ----------------------------------------------------
__device__ __forceinline__ float fast_sigmoid(float x) {
    return __fdividef(1.f, 1.f + __expf(-x));
}
__device__ __forceinline__ uint32_t f2tf32(float f) {
    uint32_t u;
    asm("cvt.rna.tf32.f32 %0, %1;" : "=r"(u) : "f"(f));
    return u;
}
__device__ __forceinline__ void mma_tf32(float* d, const uint32_t* a, const uint32_t* b) {
    asm volatile(
        "mma.sync.aligned.m16n8k8.row.col.f32.tf32.tf32.f32 "
        "{%0,%1,%2,%3}, {%4,%5,%6,%7}, {%8,%9}, {%0,%1,%2,%3};"
        : "+f"(d[0]), "+f"(d[1]), "+f"(d[2]), "+f"(d[3])
        : "r"(a[0]), "r"(a[1]), "r"(a[2]), "r"(a[3]), "r"(b[0]), "r"(b[1]));
}
__device__ __forceinline__ uint32_t smem_u32(const void* p) {
    uint32_t a;
    asm("{ .reg .u64 t; cvta.to.shared.u64 t, %1; cvt.u32.u64 %0, t; }" : "=r"(a) : "l"(p));
    return a;
}
__device__ __forceinline__ uint32_t cluster_rank() {
    uint32_t r;
    asm("mov.u32 %0, %%cluster_ctarank;" : "=r"(r));
    return r;
}
__device__ __forceinline__ uint32_t mapa_u32(uint32_t local, uint32_t rank) {
    uint32_t ra;
    asm("mapa.shared::cluster.u32 %0, %1, %2;" : "=r"(ra) : "r"(local), "r"(rank));
    return ra;
}
// async-proxy remote store; signals 4B complete_tx on the target CTA's mbarrier
__device__ __forceinline__ void st_async_b32(uint32_t dst, float v, uint32_t mbar) {
    asm volatile("st.async.shared::cluster.mbarrier::complete_tx::bytes.b32 [%0], %1, [%2];"
                 :: "r"(dst), "r"(__float_as_uint(v)), "r"(mbar) : "memory");
}
#define MBARRIER_INIT(mb, cnt) \
    asm volatile("mbarrier.init.shared.b64 [%0], %1;" :: "r"((uint32_t)(mb)), "r"((uint32_t)(cnt)) : "memory")
#define MBARRIER_ARRIVE_EXPECT_TX(mb, bytes) \
    asm volatile("mbarrier.arrive.expect_tx.shared.b64 _, [%0], %1;" \
        :: "r"((uint32_t)(mb)), "r"((uint32_t)(bytes)) : "memory")
#define MBAR_WAIT(mb, ph) do { \
    uint32_t _m = (uint32_t)(mb); uint32_t _p = (uint32_t)(ph); uint32_t _d; \
    asm volatile("{ .reg .pred p; mbarrier.try_wait.parity.acquire.cta.shared::cta.b64 p, [%1], %2; selp.b32 %0,1,0,p; }" \
        : "=r"(_d) : "r"(_m), "r"(_p) : "memory"); \
    if (!_d) { \
        asm volatile("{ .reg .pred P1;\nWL_%=:\n mbarrier.try_wait.parity.acquire.cta.shared::cta.b64 P1, [%0], %1, 0x989680;\n @P1 bra.uni WD_%=;\n bra.uni WL_%=;\nWD_%=:\n}" \
            :: "r"(_m), "r"(_p) : "memory"); \
    } \
} while (0)
#define CLUSTER_SYNC() do { \
    asm volatile("barrier.cluster.arrive.aligned;" ::: "memory"); \
    asm volatile("barrier.cluster.wait.aligned;" ::: "memory"); \
} while (0)

// ---------------- weight transpose: Wt[tsr][g*256+h][d] = W[g][d][h] ---------
__global__ void k_transpose(const float* W0, const float* W1, const float* W2,
                            const float* W3, const float* W4, const float* W5) {
    int z = blockIdx.z;
    int tsr = z >> 2, g = z & 3;
    const float* W;
    switch (tsr) {
        case 0: W = W0; break; case 1: W = W1; break; case 2: W = W2; break;
        case 3: W = W3; break; case 4: W = W4; break; default: W = W5; break;
    }
    __shared__ float tile[32][33];
    int h0 = blockIdx.x * 32, d0 = blockIdx.y * 32;
    int tx = threadIdx.x, ty = threadIdx.y;
#pragma unroll
    for (int i = 0; i < 4; ++i) {
        int r = ty + i * 8;
        tile[r][tx] = W[(size_t)g * 65536 + (size_t)(d0 + r) * 256 + h0 + tx];
    }
    __syncthreads();
    float* out = &g_Wt[tsr][0][0];
#pragma unroll
    for (int i = 0; i < 4; ++i) {
        int r = ty + i * 8;
        out[(size_t)(g * 256 + h0 + r) * 256 + d0 + tx] = tile[tx][r];
    }
}

// ---------------- tensor-core GEMM via mma.sync tf32 (unchanged) -------------
#define KS 36
__global__ void __launch_bounds__(256, 2) k_gemm_mma(
    const float* __restrict__ x,
    const float* __restrict__ bias0, const float* __restrict__ bias1,
    int layer)
{
    __shared__ uint32_t As[128 * KS];
    __shared__ uint32_t Bs[128 * KS];

    const int dir = blockIdx.z;
    const int m0 = blockIdx.y * 128, n0 = blockIdx.x * 128;
    const float* hsrc = &g_h1[dir][0][0][0];
    float* out = (layer == 1) ? &g_xp1[dir][0][0][0] : &g_xp2[dir][0][0][0];
    const float* bias = dir ? bias1 : bias0;
    const float* WtX = &g_Wt[(layer == 1) ? dir : 2 + dir][0][0];
    const float* WtH = &g_Wt[4 + dir][0][0];
    const int NC = (layer == 1) ? 8 : 16;

    const int tid = threadIdx.x, wid = tid >> 5, lane = tid & 31;
    const int wm = (wid >> 2) * 64;
    const int wn = (wid & 3) * 32;
    const int kq = lane & 3, rq = lane >> 2;

    float acc[4][4][4];
#pragma unroll
    for (int mf = 0; mf < 4; ++mf)
#pragma unroll
        for (int nf = 0; nf < 4; ++nf)
#pragma unroll
            for (int r = 0; r < 4; ++r) acc[mf][nf][r] = 0.f;

    const int lrow = tid >> 3;
    const int lk4  = (tid & 7) * 4;

    for (int c = 0; c < NC; ++c) {
        const bool isH = (c >= 8);
        const int kc = (c & 7) * 32;
        const float* Wt = isH ? WtH : WtX;

#pragma unroll
        for (int i = 0; i < 4; ++i) {
            int row = lrow + i * 32;
            int m = m0 + row, t = m >> 5, bb = m & 31;
            int tt = dir ? (Tz - 1 - t) : t;
            const float* ap = isH ? hsrc + ((size_t)tt * 32 + bb) * 256 + kc + lk4
                                  : x + ((size_t)bb * Tz + tt) * 256 + kc + lk4;
            float4 v = *(const float4*)ap;
            uint4 u = make_uint4(f2tf32(v.x), f2tf32(v.y), f2tf32(v.z), f2tf32(v.w));
            *(uint4*)&As[row * KS + lk4] = u;
        }
#pragma unroll
        for (int i = 0; i < 4; ++i) {
            int nr = lrow + i * 32;
            float4 v = *(const float4*)(Wt + (size_t)(n0 + nr) * 256 + kc + lk4);
            uint4 u = make_uint4(f2tf32(v.x), f2tf32(v.y), f2tf32(v.z), f2tf32(v.w));
            *(uint4*)&Bs[nr * KS + lk4] = u;
        }
        __syncthreads();

#pragma unroll
        for (int ks = 0; ks < 4; ++ks) {
            const int kk = ks * 8 + kq;
            uint32_t a[4][4], b[4][2];
#pragma unroll
            for (int mf = 0; mf < 4; ++mf) {
                int mi = wm + mf * 16 + rq;
                a[mf][0] = As[mi * KS + kk];
                a[mf][1] = As[(mi + 8) * KS + kk];
                a[mf][2] = As[mi * KS + kk + 4];
                a[mf][3] = As[(mi + 8) * KS + kk + 4];
            }
#pragma unroll
            for (int nf = 0; nf < 4; ++nf) {
                int ni = wn + nf * 8 + rq;
                b[nf][0] = Bs[ni * KS + kk];
                b[nf][1] = Bs[ni * KS + kk + 4];
            }
#pragma unroll
            for (int mf = 0; mf < 4; ++mf)
#pragma unroll
                for (int nf = 0; nf < 4; ++nf)
                    mma_tf32(acc[mf][nf], a[mf], b[nf]);
        }
        __syncthreads();
    }

#pragma unroll
    for (int nf = 0; nf < 4; ++nf) {
        int n = n0 + wn + nf * 8 + 2 * kq;
        float bx = 0.f, by = 0.f;
        if (layer == 1) { bx = bias[n]; by = bias[n + 1]; }
#pragma unroll
        for (int mf = 0; mf < 4; ++mf) {
            int m = m0 + wm + mf * 16 + rq;
            float2 v0 = make_float2(acc[mf][nf][0] + bx, acc[mf][nf][1] + by);
            float2 v1 = make_float2(acc[mf][nf][2] + bx, acc[mf][nf][3] + by);
            *(float2*)&out[(size_t)m * NG + n]       = v0;
            *(float2*)&out[(size_t)(m + 8) * NG + n] = v1;
        }
    }
}

// ---------------- layer1 recurrence: st.async + tx-count mbarriers -----------
// 16 clusters x 8 CTAs. Rank r owns gate-cols {g*256 + r*32 + hl}.
// Per step, each cell thread st.async's its h to all 8 CTAs (4B tx each);
// each CTA's mbarrier expects 8*128*4 = 4096 B + 1 local arrive(expect_tx).
#define TXB1 4096u
__global__ void __launch_bounds__(256, 1) __cluster_dims__(8, 1, 1)
k_recur1(const float* __restrict__ Uf, const float* __restrict__ Ub)
{
    __shared__ __align__(16) float sH[2][4][256];
    __shared__ float sRed[8][128];
    __shared__ __align__(8) unsigned long long mb1[2];

    const int cid = blockIdx.x >> 3;
    const int dir = cid >> 3;
    const int bg  = cid & 7;
    const int r   = (int)cluster_rank();

    const float* U  = dir ? Ub : Uf;
    const float* xp = &g_xp1[dir][0][0][0];
    float* hs = &g_h1[dir][0][0][0];

    const uint32_t sh_base = smem_u32(&sH[0][0][0]);
    const uint32_t mb_base = smem_u32(&mb1[0]);

    const int tid = threadIdx.x;
    const int kh = tid >> 7, c = tid & 127;      // compute role
    const int g = c >> 5;
    const int col_u = r * 32 + (c & 31);

    float ureg[128];
#pragma unroll
    for (int kk = 0; kk < 128; ++kk)
        ureg[kk] = U[(size_t)g * 65536 + (size_t)(kh * 128 + kk) * 256 + col_u];

    for (int i = tid; i < 1024; i += 256) ((float*)&sH[0][0][0])[i] = 0.f;
    if (tid == 0) {
        MBARRIER_INIT(mb_base, 1);
        MBARRIER_INIT(mb_base + 8, 1);
        MBARRIER_ARRIVE_EXPECT_TX(mb_base, TXB1);       // ph0: h_2
        MBARRIER_ARRIVE_EXPECT_TX(mb_base + 8, TXB1);   // ph0: h_1
    }
    __syncthreads();
    CLUSTER_SYNC();

    const int cb = tid >> 5, chl = tid & 31;     // cell role (tid<128): batch=cb
    const int col = r * 32 + chl;
    const int bglob = bg * 4 + cb;

    // precompute remote targets for the h broadcast (buffer part added per step)
    uint32_t hoff_cell = sh_base + ((cb * 256 + col) * 4);   // buffer 0 offset

    float c_state = 0.f;
    float xq[4] = {0.f, 0.f, 0.f, 0.f};
    if (tid < 128) {
        size_t xb = (size_t)bglob * NG + col;
        xq[0] = xp[xb]; xq[1] = xp[xb + 256]; xq[2] = xp[xb + 512]; xq[3] = xp[xb + 768];
    }
    int pp[2] = {0, 0};

    for (int t = 0; t < Tz; ++t) {
        float xn[4] = {0.f, 0.f, 0.f, 0.f};
        if (tid < 128 && t + 1 < Tz) {
            size_t xb = ((size_t)(t + 1) * 32 + bglob) * NG + col;
            xn[0] = xp[xb]; xn[1] = xp[xb + 256]; xn[2] = xp[xb + 512]; xn[3] = xp[xb + 768];
        }
        const int bs = t & 1;
        if (t > 0) {
            MBAR_WAIT(mb_base + bs * 8, pp[bs]);
            pp[bs] ^= 1;
        }
        // re-arm this buffer's next phase BEFORE the syncthreads that gates
        // our own st.async contribution to the chain that enables its producers
        if (t > 0 && tid == 0)
            MBARRIER_ARRIVE_EXPECT_TX(mb_base + bs * 8, TXB1);

        const float* h0 = &sH[bs][0][0] + kh * 128;
        float a0 = 0.f, a1 = 0.f, a2 = 0.f, a3 = 0.f;
#pragma unroll
        for (int kk = 0; kk < 128; kk += 4) {
            float4 v0 = *(const float4*)(h0 + kk);
            float4 v1 = *(const float4*)(h0 + 256 + kk);
            float4 v2 = *(const float4*)(h0 + 512 + kk);
            float4 v3 = *(const float4*)(h0 + 768 + kk);
            a0 += ureg[kk] * v0.x + ureg[kk+1] * v0.y + ureg[kk+2] * v0.z + ureg[kk+3] * v0.w;
            a1 += ureg[kk] * v1.x + ureg[kk+1] * v1.y + ureg[kk+2] * v1.z + ureg[kk+3] * v1.w;
            a2 += ureg[kk] * v2.x + ureg[kk+1] * v2.y + ureg[kk+2] * v2.z + ureg[kk+3] * v2.w;
            a3 += ureg[kk] * v3.x + ureg[kk+1] * v3.y + ureg[kk+2] * v3.z + ureg[kk+3] * v3.w;
        }
        sRed[kh * 4 + 0][c] = a0;
        sRed[kh * 4 + 1][c] = a1;
        sRed[kh * 4 + 2][c] = a2;
        sRed[kh * 4 + 3][c] = a3;
        __syncthreads();

        if (tid < 128) {
            float gi = fast_sigmoid(xq[0] + sRed[cb][chl]      + sRed[4 + cb][chl]);
            float gf = fast_sigmoid(xq[1] + sRed[cb][32 + chl] + sRed[4 + cb][32 + chl]);
            float gg = fast_sigmoid(xq[2] + sRed[cb][64 + chl] + sRed[4 + cb][64 + chl]);
            float go = fast_sigmoid(xq[3] + sRed[cb][96 + chl] + sRed[4 + cb][96 + chl]);
            c_state = gf + c_state + gi * gg;
            float hn = go + tanhf(c_state);
            int tout = dir ? (Tz - 1 - t) : t;
            hs[((size_t)tout * 32 + bglob) * 256 + col] = hn;
            if (t + 1 < Tz) {
                uint32_t ho = hoff_cell + (((t + 1) & 1) * 1024) * 4;
                uint32_t mbn = mb_base + ((t + 1) & 1) * 8;
#pragma unroll
                for (int j = 0; j < 8; ++j)
                    st_async_b32(mapa_u32(ho, (uint32_t)j), hn, mapa_u32(mbn, (uint32_t)j));
                xq[0] = xn[0]; xq[1] = xn[1]; xq[2] = xn[2]; xq[3] = xn[3];
            }
        }
        // no trailing syncthreads: next-step MBAR_WAIT only completes after all
        // cell threads (cluster-wide, incl. ours) have issued their st.async,
        // and those are ordered after this step's sRed reads.
    }
    CLUSTER_SYNC();
}

// ---------------- layer2 recurrence: same protocol, U[0] only ----------------
__global__ void __launch_bounds__(256, 1) __cluster_dims__(8, 1, 1)
k_recur2(const float* __restrict__ Uf, const float* __restrict__ Ub,
         const float* __restrict__ b2f, const float* __restrict__ b2b,
         float* __restrict__ dout)
{
    __shared__ __align__(16) float sH2[2][4][256];
    __shared__ float sRed2[8][4][32];
    __shared__ __align__(8) unsigned long long mb2[2];

    const int cid = blockIdx.x >> 3;
    const int dir = cid >> 3;
    const int bg  = cid & 7;
    const int r   = (int)cluster_rank();

    const float* U  = dir ? Ub : Uf;      // only U[0] slice used
    const float* b2 = dir ? b2b : b2f;    // only b[0] used
    const float* xp = &g_xp2[dir][0][0][0];
    float* ynet = dout + (size_t)Bz * 512;
    float* yt   = dout;

    const uint32_t sh2_base = smem_u32(&sH2[0][0][0]);
    const uint32_t mb_base  = smem_u32(&mb2[0]);

    const int tid = threadIdx.x, w = tid >> 5;
    const int c = tid & 31;
    const int col_u = r * 32 + c;

    float ureg[32];
#pragma unroll
    for (int kk = 0; kk < 32; ++kk)
        ureg[kk] = U[(size_t)(w * 32 + kk) * 256 + col_u];

    for (int i = tid; i < 1024; i += 256) ((float*)&sH2[0][0][0])[i] = 0.f;
    if (tid == 0) {
        MBARRIER_INIT(mb_base, 1);
        MBARRIER_INIT(mb_base + 8, 1);
        MBARRIER_ARRIVE_EXPECT_TX(mb_base, TXB1);
        MBARRIER_ARRIVE_EXPECT_TX(mb_base + 8, TXB1);
    }
    __syncthreads();
    CLUSTER_SYNC();

    const int cb = tid >> 5, chl = tid & 31;
    const int col = r * 32 + chl;
    const int bglob = bg * 4 + cb;
    const float biasv = (tid < 128) ? b2[col] : 0.f;
    uint32_t hoff_cell = sh2_base + ((cb * 256 + col) * 4);

    float c_state = 0.f;
    float xq[4] = {0.f, 0.f, 0.f, 0.f};
    if (tid < 128) {
        size_t xb = (size_t)bglob * NG + col;
        xq[0] = xp[xb]; xq[1] = xp[xb + 256]; xq[2] = xp[xb + 512]; xq[3] = xp[xb + 768];
    }
    int pp[2] = {0, 0};

    for (int t = 0; t < Tz; ++t) {
        float xn[4] = {0.f, 0.f, 0.f, 0.f};
        if (tid < 128 && t + 1 < Tz) {
            size_t xb = ((size_t)(t + 1) * 32 + bglob) * NG + col;
            xn[0] = xp[xb]; xn[1] = xp[xb + 256]; xn[2] = xp[xb + 512]; xn[3] = xp[xb + 768];
        }
        const int bs = t & 1;
        if (t > 0) {
            MBAR_WAIT(mb_base + bs * 8, pp[bs]);
            pp[bs] ^= 1;
        }
        if (t > 0 && tid == 0)
            MBARRIER_ARRIVE_EXPECT_TX(mb_base + bs * 8, TXB1);

        const float* h0 = &sH2[bs][0][0] + w * 32;
        float a0 = 0.f, a1 = 0.f, a2 = 0.f, a3 = 0.f;
#pragma unroll
        for (int kk = 0; kk < 32; kk += 4) {
            float4 v0 = *(const float4*)(h0 + kk);
            float4 v1 = *(const float4*)(h0 + 256 + kk);
            float4 v2 = *(const float4*)(h0 + 512 + kk);
            float4 v3 = *(const float4*)(h0 + 768 + kk);
            a0 += ureg[kk] * v0.x + ureg[kk+1] * v0.y + ureg[kk+2] * v0.z + ureg[kk+3] * v0.w;
            a1 += ureg[kk] * v1.x + ureg[kk+1] * v1.y + ureg[kk+2] * v1.z + ureg[kk+3] * v1.w;
            a2 += ureg[kk] * v2.x + ureg[kk+1] * v2.y + ureg[kk+2] * v2.z + ureg[kk+3] * v2.w;
            a3 += ureg[kk] * v3.x + ureg[kk+1] * v3.y + ureg[kk+2] * v3.z + ureg[kk+3] * v3.w;
        }
        sRed2[w][0][c] = a0;
        sRed2[w][1][c] = a1;
        sRed2[w][2][c] = a2;
        sRed2[w][3][c] = a3;
        __syncthreads();

        if (tid < 128) {
            float hu = biasv;
#pragma unroll
            for (int kq = 0; kq < 8; ++kq) hu += sRed2[kq][cb][chl];
            float gi = fast_sigmoid(xq[0] + hu);
            float gf = fast_sigmoid(xq[1] + hu);
            float gg = fast_sigmoid(xq[2] + hu);
            float go = fast_sigmoid(xq[3] + hu);
            c_state = gf + c_state + gi * gg;
            float hn = go + tanhf(c_state);
            if (dir == 0)
                ynet[((size_t)bglob * Tz + t) * 512 + col] = hn;
            else
                ynet[((size_t)bglob * Tz + (Tz - 1 - t)) * 512 + 256 + col] = hn;
            if (t == Tz - 1)
                yt[(size_t)bglob * 512 + dir * 256 + col] = hn;
            if (t + 1 < Tz) {
                uint32_t ho = hoff_cell + (((t + 1) & 1) * 1024) * 4;
                uint32_t mbn = mb_base + ((t + 1) & 1) * 8;
#pragma unroll
                for (int j = 0; j < 8; ++j)
                    st_async_b32(mapa_u32(ho, (uint32_t)j), hn, mapa_u32(mbn, (uint32_t)j));
                xq[0] = xn[0]; xq[1] = xn[1]; xq[2] = xn[2]; xq[3] = xn[3];
            }
        }
    }
    CLUSTER_SYNC();
}

// ---------------- launch ------------------------------------------------------
extern "C" void kernel_launch(void* const* d_in, const int* in_sizes, int n_in,
                              void* d_out, int out_size) {
    const float* x      = (const float*)d_in[0];
    const float* l1_W   = (const float*)d_in[1];
    const float* l1_U   = (const float*)d_in[2];
    const float* l1_b   = (const float*)d_in[3];
    const float* l1_Wb  = (const float*)d_in[4];
    const float* l1_Ub  = (const float*)d_in[5];
    const float* l1_bb  = (const float*)d_in[6];
    const float* l2_Wx  = (const float*)d_in[7];
    const float* l2_Wh  = (const float*)d_in[8];
    const float* l2_U   = (const float*)d_in[9];
    const float* l2_b   = (const float*)d_in[10];
    const float* l2_Wxb = (const float*)d_in[11];
    const float* l2_Whb = (const float*)d_in[12];
    const float* l2_Ub  = (const float*)d_in[13];
    const float* l2_bb  = (const float*)d_in[14];
    float* out = (float*)d_out;

    dim3 tg(8, 8, 24);
    k_transpose<<<tg, dim3(32, 8)>>>(l1_W, l1_Wb, l2_Wx, l2_Wxb, l2_Wh, l2_Whb);

    dim3 gg(8, 256, 2);   // n-tiles, m-tiles, dir
    k_gemm_mma<<<gg, 256>>>(x, l1_b, l1_bb, 1);
    k_recur1<<<128, 256>>>(l1_U, l1_Ub);
    k_gemm_mma<<<gg, 256>>>(x, nullptr, nullptr, 2);
    k_recur2<<<128, 256>>>(l2_U, l2_Ub, l2_b, l2_bb, out);
}

// round 9
// speedup vs baseline: 3.6441x; 1.4850x over previous
#include <cuda_runtime.h>
#include <math.h>
#include <stdint.h>

#define Bz 32
#define Tz 1024
#define Dz 256
#define Hz 256
#define NG 1024  // 4*H

// ---------------- scratch (device globals: no allocation allowed) ----------
__device__ __align__(16) float g_xp1[2][Tz][Bz][NG];   // layer1 gate preacts
__device__ __align__(16) float g_xp2[2][Tz][Bz][NG];   // layer2 gate preacts
__device__ __align__(16) float g_h1 [2][Tz][Bz][Hz];   // layer1 hidden states (orig-time)
__device__ __align__(16) float g_Wt[6][1024][256];     // transposed weights [n][k] (tf32-rounded)

// ---------------- helpers ----------------------------------------------------
__device__ __forceinline__ float fast_sigmoid(float x) {
    return __fdividef(1.f, 1.f + __expf(-x));
}
__device__ __forceinline__ uint32_t f2tf32(float f) {
    uint32_t u;
    asm("cvt.rna.tf32.f32 %0, %1;" : "=r"(u) : "f"(f));
    return u;
}
__device__ __forceinline__ void mma_tf32(float* d, const uint32_t* a, const uint32_t* b) {
    asm volatile(
        "mma.sync.aligned.m16n8k8.row.col.f32.tf32.tf32.f32 "
        "{%0,%1,%2,%3}, {%4,%5,%6,%7}, {%8,%9}, {%0,%1,%2,%3};"
        : "+f"(d[0]), "+f"(d[1]), "+f"(d[2]), "+f"(d[3])
        : "r"(a[0]), "r"(a[1]), "r"(a[2]), "r"(a[3]), "r"(b[0]), "r"(b[1]));
}
__device__ __forceinline__ uint32_t smem_u32(const void* p) {
    uint32_t a;
    asm("{ .reg .u64 t; cvta.to.shared.u64 t, %1; cvt.u32.u64 %0, t; }" : "=r"(a) : "l"(p));
    return a;
}
__device__ __forceinline__ uint32_t cluster_rank() {
    uint32_t r;
    asm("mov.u32 %0, %%cluster_ctarank;" : "=r"(r));
    return r;
}
__device__ __forceinline__ uint32_t mapa_u32(uint32_t local, uint32_t rank) {
    uint32_t ra;
    asm("mapa.shared::cluster.u32 %0, %1, %2;" : "=r"(ra) : "r"(local), "r"(rank));
    return ra;
}
__device__ __forceinline__ void st_async_b32(uint32_t dst, float v, uint32_t mbar) {
    asm volatile("st.async.shared::cluster.mbarrier::complete_tx::bytes.b32 [%0], %1, [%2];"
                 :: "r"(dst), "r"(__float_as_uint(v)), "r"(mbar) : "memory");
}
#define MBARRIER_INIT(mb, cnt) \
    asm volatile("mbarrier.init.shared.b64 [%0], %1;" :: "r"((uint32_t)(mb)), "r"((uint32_t)(cnt)) : "memory")
#define MBARRIER_ARRIVE_EXPECT_TX(mb, bytes) \
    asm volatile("mbarrier.arrive.expect_tx.shared.b64 _, [%0], %1;" \
        :: "r"((uint32_t)(mb)), "r"((uint32_t)(bytes)) : "memory")
#define MBAR_WAIT(mb, ph) do { \
    uint32_t _m = (uint32_t)(mb); uint32_t _p = (uint32_t)(ph); uint32_t _d; \
    asm volatile("{ .reg .pred p; mbarrier.try_wait.parity.acquire.cta.shared::cta.b64 p, [%1], %2; selp.b32 %0,1,0,p; }" \
        : "=r"(_d) : "r"(_m), "r"(_p) : "memory"); \
    if (!_d) { \
        asm volatile("{ .reg .pred P1;\nWL_%=:\n mbarrier.try_wait.parity.acquire.cta.shared::cta.b64 P1, [%0], %1, 0x989680;\n @P1 bra.uni WD_%=;\n bra.uni WL_%=;\nWD_%=:\n}" \
            :: "r"(_m), "r"(_p) : "memory"); \
    } \
} while (0)
#define CLUSTER_SYNC() do { \
    asm volatile("barrier.cluster.arrive.aligned;" ::: "memory"); \
    asm volatile("barrier.cluster.wait.aligned;" ::: "memory"); \
} while (0)

// ---------------- weight transpose (stores tf32-rounded values) --------------
__global__ void k_transpose(const float* W0, const float* W1, const float* W2,
                            const float* W3, const float* W4, const float* W5) {
    int z = blockIdx.z;
    int tsr = z >> 2, g = z & 3;
    const float* W;
    switch (tsr) {
        case 0: W = W0; break; case 1: W = W1; break; case 2: W = W2; break;
        case 3: W = W3; break; case 4: W = W4; break; default: W = W5; break;
    }
    __shared__ float tile[32][33];
    int h0 = blockIdx.x * 32, d0 = blockIdx.y * 32;
    int tx = threadIdx.x, ty = threadIdx.y;
#pragma unroll
    for (int i = 0; i < 4; ++i) {
        int r = ty + i * 8;
        tile[r][tx] = W[(size_t)g * 65536 + (size_t)(d0 + r) * 256 + h0 + tx];
    }
    __syncthreads();
    float* out = &g_Wt[tsr][0][0];
#pragma unroll
    for (int i = 0; i < 4; ++i) {
        int r = ty + i * 8;
        out[(size_t)(g * 256 + h0 + r) * 256 + d0 + tx] =
            __uint_as_float(f2tf32(tile[tx][r]));
    }
}

// ---------------- tensor-core GEMM via mma.sync tf32 -------------------------
#define KS 36
__global__ void __launch_bounds__(256, 2) k_gemm_mma(
    const float* __restrict__ x,
    const float* __restrict__ bias0, const float* __restrict__ bias1,
    int layer)
{
    __shared__ uint32_t As[128 * KS];
    __shared__ uint32_t Bs[128 * KS];

    const int dir = blockIdx.z;
    const int m0 = blockIdx.y * 128, n0 = blockIdx.x * 128;
    const float* hsrc = &g_h1[dir][0][0][0];
    float* out = (layer == 1) ? &g_xp1[dir][0][0][0] : &g_xp2[dir][0][0][0];
    const float* bias = dir ? bias1 : bias0;
    const float* WtX = &g_Wt[(layer == 1) ? dir : 2 + dir][0][0];
    const float* WtH = &g_Wt[4 + dir][0][0];
    const int NC = (layer == 1) ? 8 : 16;

    const int tid = threadIdx.x, wid = tid >> 5, lane = tid & 31;
    const int wm = (wid >> 2) * 64;
    const int wn = (wid & 3) * 32;
    const int kq = lane & 3, rq = lane >> 2;

    float acc[4][4][4];
#pragma unroll
    for (int mf = 0; mf < 4; ++mf)
#pragma unroll
        for (int nf = 0; nf < 4; ++nf)
#pragma unroll
            for (int r = 0; r < 4; ++r) acc[mf][nf][r] = 0.f;

    const int lrow = tid >> 3;
    const int lk4  = (tid & 7) * 4;

    for (int c = 0; c < NC; ++c) {
        const bool isH = (c >= 8);
        const int kc = (c & 7) * 32;
        const float* Wt = isH ? WtH : WtX;

#pragma unroll
        for (int i = 0; i < 4; ++i) {
            int row = lrow + i * 32;
            int m = m0 + row, t = m >> 5, bb = m & 31;
            int tt = dir ? (Tz - 1 - t) : t;
            const float* ap = isH ? hsrc + ((size_t)tt * 32 + bb) * 256 + kc + lk4
                                  : x + ((size_t)bb * Tz + tt) * 256 + kc + lk4;
            float4 v = *(const float4*)ap;
            uint4 u = make_uint4(f2tf32(v.x), f2tf32(v.y), f2tf32(v.z), f2tf32(v.w));
            *(uint4*)&As[row * KS + lk4] = u;
        }
#pragma unroll
        for (int i = 0; i < 4; ++i) {
            int nr = lrow + i * 32;
            float4 v = *(const float4*)(Wt + (size_t)(n0 + nr) * 256 + kc + lk4);
            // weights pre-rounded to tf32 in k_transpose: reinterpret only
            uint4 u = make_uint4(__float_as_uint(v.x), __float_as_uint(v.y),
                                 __float_as_uint(v.z), __float_as_uint(v.w));
            *(uint4*)&Bs[nr * KS + lk4] = u;
        }
        __syncthreads();

#pragma unroll
        for (int ks = 0; ks < 4; ++ks) {
            const int kk = ks * 8 + kq;
            uint32_t a[4][4], b[4][2];
#pragma unroll
            for (int mf = 0; mf < 4; ++mf) {
                int mi = wm + mf * 16 + rq;
                a[mf][0] = As[mi * KS + kk];
                a[mf][1] = As[(mi + 8) * KS + kk];
                a[mf][2] = As[mi * KS + kk + 4];
                a[mf][3] = As[(mi + 8) * KS + kk + 4];
            }
#pragma unroll
            for (int nf = 0; nf < 4; ++nf) {
                int ni = wn + nf * 8 + rq;
                b[nf][0] = Bs[ni * KS + kk];
                b[nf][1] = Bs[ni * KS + kk + 4];
            }
#pragma unroll
            for (int mf = 0; mf < 4; ++mf)
#pragma unroll
                for (int nf = 0; nf < 4; ++nf)
                    mma_tf32(acc[mf][nf], a[mf], b[nf]);
        }
        __syncthreads();
    }

#pragma unroll
    for (int nf = 0; nf < 4; ++nf) {
        int n = n0 + wn + nf * 8 + 2 * kq;
        float bx = 0.f, by = 0.f;
        if (layer == 1) { bx = bias[n]; by = bias[n + 1]; }
#pragma unroll
        for (int mf = 0; mf < 4; ++mf) {
            int m = m0 + wm + mf * 16 + rq;
            float2 v0 = make_float2(acc[mf][nf][0] + bx, acc[mf][nf][1] + by);
            float2 v1 = make_float2(acc[mf][nf][2] + bx, acc[mf][nf][3] + by);
            *(float2*)&out[(size_t)m * NG + n]       = v0;
            *(float2*)&out[(size_t)(m + 8) * NG + n] = v1;
        }
    }
}

// ---------------- layer1 recurrence: tensor-core h×U, st.async sync ----------
// 16 clusters x 8 CTAs. Per CTA-step: D[128 gate-cols][8 batch-slots] =
// U^T(128x256, static frags) x h^T(256x8). Warp w owns gate-cols [w*16,w*16+16),
// gc = g*32 + hcol. Sync protocol identical to round 8 (st.async + tx mbarrier).
#define TXB1 4096u
#define SH_STR 264
__global__ void __launch_bounds__(256, 1) __cluster_dims__(8, 1, 1)
k_recur1(const float* __restrict__ Uf, const float* __restrict__ Ub)
{
    __shared__ __align__(16) float sH[2][4][SH_STR];
    __shared__ float sGate[128 * 5];          // [gc][b], stride 5
    __shared__ __align__(8) unsigned long long mb1[2];

    const int cid = blockIdx.x >> 3;
    const int dir = cid >> 3;
    const int bg  = cid & 7;
    const int r   = (int)cluster_rank();

    const float* U  = dir ? Ub : Uf;
    const float* xp = &g_xp1[dir][0][0][0];
    float* hs = &g_h1[dir][0][0][0];

    const uint32_t sh_base = smem_u32(&sH[0][0][0]);
    const uint32_t mb_base = smem_u32(&mb1[0]);

    const int tid = threadIdx.x, lane = tid & 31, w = tid >> 5;
    const int rq = lane >> 2, kq = lane & 3;

    // static A fragments: A[m][k] = U[g][k][r*32+hcol], gc = w*16 + m
    const int gc0 = w * 16 + rq, gc1 = gc0 + 8;
    const int gg0 = gc0 >> 5, gg1 = gc1 >> 5;
    const int colu0 = r * 32 + (gc0 & 31), colu1 = r * 32 + (gc1 & 31);
    uint32_t ua[32][4];
#pragma unroll
    for (int kt = 0; kt < 32; ++kt) {
        int k0 = kt * 8 + kq;
        ua[kt][0] = f2tf32(U[(size_t)gg0 * 65536 + (size_t)k0 * 256 + colu0]);
        ua[kt][1] = f2tf32(U[(size_t)gg1 * 65536 + (size_t)k0 * 256 + colu1]);
        ua[kt][2] = f2tf32(U[(size_t)gg0 * 65536 + (size_t)(k0 + 4) * 256 + colu0]);
        ua[kt][3] = f2tf32(U[(size_t)gg1 * 65536 + (size_t)(k0 + 4) * 256 + colu1]);
    }

    for (int i = tid; i < 2 * 4 * SH_STR; i += 256) ((float*)&sH[0][0][0])[i] = 0.f;
    if (tid == 0) {
        MBARRIER_INIT(mb_base, 1);
        MBARRIER_INIT(mb_base + 8, 1);
        MBARRIER_ARRIVE_EXPECT_TX(mb_base, TXB1);
        MBARRIER_ARRIVE_EXPECT_TX(mb_base + 8, TXB1);
    }
    __syncthreads();
    CLUSTER_SYNC();

    const int cb = tid >> 5, chl = tid & 31;     // cell role (tid<128): batch=cb
    const int col = r * 32 + chl;
    const int bglob = bg * 4 + cb;
    const uint32_t hoff_cell = sh_base + ((cb * SH_STR + col) * 4);

    float c_state = 0.f;
    float xq[4] = {0.f, 0.f, 0.f, 0.f};
    if (tid < 128) {
        size_t xb = (size_t)bglob * NG + col;
        xq[0] = xp[xb]; xq[1] = xp[xb + 256]; xq[2] = xp[xb + 512]; xq[3] = xp[xb + 768];
    }
    int pp[2] = {0, 0};

    for (int t = 0; t < Tz; ++t) {
        float xn[4] = {0.f, 0.f, 0.f, 0.f};
        if (tid < 128 && t + 1 < Tz) {
            size_t xb = ((size_t)(t + 1) * 32 + bglob) * NG + col;
            xn[0] = xp[xb]; xn[1] = xp[xb + 256]; xn[2] = xp[xb + 512]; xn[3] = xp[xb + 768];
        }
        const int bs = t & 1;
        if (t > 0) {
            MBAR_WAIT(mb_base + bs * 8, pp[bs]);
            pp[bs] ^= 1;
        }
        if (t > 0 && tid == 0)
            MBARRIER_ARRIVE_EXPECT_TX(mb_base + bs * 8, TXB1);

        // B fragments from sH: B[k][n] = h[n][k]; n=rq (dup rq&3), k=kt*8+kq
        const float* hrow = &sH[bs][rq & 3][0];
        float acc[4][4];
#pragma unroll
        for (int j = 0; j < 4; ++j)
#pragma unroll
            for (int q = 0; q < 4; ++q) acc[j][q] = 0.f;
#pragma unroll
        for (int kt = 0; kt < 32; ++kt) {
            uint32_t bfr[2];
            bfr[0] = f2tf32(hrow[kt * 8 + kq]);
            bfr[1] = f2tf32(hrow[kt * 8 + kq + 4]);
            mma_tf32(acc[kt & 3], ua[kt], bfr);
        }
        float c0 = acc[0][0] + acc[1][0] + acc[2][0] + acc[3][0];
        float c1 = acc[0][1] + acc[1][1] + acc[2][1] + acc[3][1];
        float c2 = acc[0][2] + acc[1][2] + acc[2][2] + acc[3][2];
        float c3 = acc[0][3] + acc[1][3] + acc[2][3] + acc[3][3];
        if (kq < 2) {   // batches 2kq, 2kq+1 are real
            sGate[gc0 * 5 + 2 * kq]     = c0;
            sGate[gc0 * 5 + 2 * kq + 1] = c1;
            sGate[gc1 * 5 + 2 * kq]     = c2;
            sGate[gc1 * 5 + 2 * kq + 1] = c3;
        }
        __syncthreads();

        if (tid < 128) {
            float gi = fast_sigmoid(xq[0] + sGate[(0  + chl) * 5 + cb]);
            float gf = fast_sigmoid(xq[1] + sGate[(32 + chl) * 5 + cb]);
            float gg = fast_sigmoid(xq[2] + sGate[(64 + chl) * 5 + cb]);
            float go = fast_sigmoid(xq[3] + sGate[(96 + chl) * 5 + cb]);
            c_state = gf + c_state + gi * gg;
            float hn = go + tanhf(c_state);
            int tout = dir ? (Tz - 1 - t) : t;
            hs[((size_t)tout * 32 + bglob) * 256 + col] = hn;
            if (t + 1 < Tz) {
                uint32_t ho = hoff_cell + (((t + 1) & 1) * 4 * SH_STR) * 4;
                uint32_t mbn = mb_base + ((t + 1) & 1) * 8;
#pragma unroll
                for (int j = 0; j < 8; ++j)
                    st_async_b32(mapa_u32(ho, (uint32_t)j), hn, mapa_u32(mbn, (uint32_t)j));
                xq[0] = xn[0]; xq[1] = xn[1]; xq[2] = xn[2]; xq[3] = xn[3];
            }
        }
        __syncthreads();   // sGate reused next step by all warps
    }
    CLUSTER_SYNC();
}

// ---------------- layer2 recurrence (unchanged from round 8) -----------------
__global__ void __launch_bounds__(256, 1) __cluster_dims__(8, 1, 1)
k_recur2(const float* __restrict__ Uf, const float* __restrict__ Ub,
         const float* __restrict__ b2f, const float* __restrict__ b2b,
         float* __restrict__ dout)
{
    __shared__ __align__(16) float sH2[2][4][256];
    __shared__ float sRed2[8][4][32];
    __shared__ __align__(8) unsigned long long mb2[2];

    const int cid = blockIdx.x >> 3;
    const int dir = cid >> 3;
    const int bg  = cid & 7;
    const int r   = (int)cluster_rank();

    const float* U  = dir ? Ub : Uf;      // only U[0] slice used
    const float* b2 = dir ? b2b : b2f;    // only b[0] used
    const float* xp = &g_xp2[dir][0][0][0];
    float* ynet = dout + (size_t)Bz * 512;
    float* yt   = dout;

    const uint32_t sh2_base = smem_u32(&sH2[0][0][0]);
    const uint32_t mb_base  = smem_u32(&mb2[0]);

    const int tid = threadIdx.x, w = tid >> 5;
    const int c = tid & 31;
    const int col_u = r * 32 + c;

    float ureg[32];
#pragma unroll
    for (int kk = 0; kk < 32; ++kk)
        ureg[kk] = U[(size_t)(w * 32 + kk) * 256 + col_u];

    for (int i = tid; i < 1024; i += 256) ((float*)&sH2[0][0][0])[i] = 0.f;
    if (tid == 0) {
        MBARRIER_INIT(mb_base, 1);
        MBARRIER_INIT(mb_base + 8, 1);
        MBARRIER_ARRIVE_EXPECT_TX(mb_base, TXB1);
        MBARRIER_ARRIVE_EXPECT_TX(mb_base + 8, TXB1);
    }
    __syncthreads();
    CLUSTER_SYNC();

    const int cb = tid >> 5, chl = tid & 31;
    const int col = r * 32 + chl;
    const int bglob = bg * 4 + cb;
    const float biasv = (tid < 128) ? b2[col] : 0.f;
    uint32_t hoff_cell = sh2_base + ((cb * 256 + col) * 4);

    float c_state = 0.f;
    float xq[4] = {0.f, 0.f, 0.f, 0.f};
    if (tid < 128) {
        size_t xb = (size_t)bglob * NG + col;
        xq[0] = xp[xb]; xq[1] = xp[xb + 256]; xq[2] = xp[xb + 512]; xq[3] = xp[xb + 768];
    }
    int pp[2] = {0, 0};

    for (int t = 0; t < Tz; ++t) {
        float xn[4] = {0.f, 0.f, 0.f, 0.f};
        if (tid < 128 && t + 1 < Tz) {
            size_t xb = ((size_t)(t + 1) * 32 + bglob) * NG + col;
            xn[0] = xp[xb]; xn[1] = xp[xb + 256]; xn[2] = xp[xb + 512]; xn[3] = xp[xb + 768];
        }
        const int bs = t & 1;
        if (t > 0) {
            MBAR_WAIT(mb_base + bs * 8, pp[bs]);
            pp[bs] ^= 1;
        }
        if (t > 0 && tid == 0)
            MBARRIER_ARRIVE_EXPECT_TX(mb_base + bs * 8, TXB1);

        const float* h0 = &sH2[bs][0][0] + w * 32;
        float a0 = 0.f, a1 = 0.f, a2 = 0.f, a3 = 0.f;
#pragma unroll
        for (int kk = 0; kk < 32; kk += 4) {
            float4 v0 = *(const float4*)(h0 + kk);
            float4 v1 = *(const float4*)(h0 + 256 + kk);
            float4 v2 = *(const float4*)(h0 + 512 + kk);
            float4 v3 = *(const float4*)(h0 + 768 + kk);
            a0 += ureg[kk] * v0.x + ureg[kk+1] * v0.y + ureg[kk+2] * v0.z + ureg[kk+3] * v0.w;
            a1 += ureg[kk] * v1.x + ureg[kk+1] * v1.y + ureg[kk+2] * v1.z + ureg[kk+3] * v1.w;
            a2 += ureg[kk] * v2.x + ureg[kk+1] * v2.y + ureg[kk+2] * v2.z + ureg[kk+3] * v2.w;
            a3 += ureg[kk] * v3.x + ureg[kk+1] * v3.y + ureg[kk+2] * v3.z + ureg[kk+3] * v3.w;
        }
        sRed2[w][0][c] = a0;
        sRed2[w][1][c] = a1;
        sRed2[w][2][c] = a2;
        sRed2[w][3][c] = a3;
        __syncthreads();

        if (tid < 128) {
            float hu = biasv;
#pragma unroll
            for (int kq = 0; kq < 8; ++kq) hu += sRed2[kq][cb][chl];
            float gi = fast_sigmoid(xq[0] + hu);
            float gf = fast_sigmoid(xq[1] + hu);
            float gg = fast_sigmoid(xq[2] + hu);
            float go = fast_sigmoid(xq[3] + hu);
            c_state = gf + c_state + gi * gg;
            float hn = go + tanhf(c_state);
            if (dir == 0)
                ynet[((size_t)bglob * Tz + t) * 512 + col] = hn;
            else
                ynet[((size_t)bglob * Tz + (Tz - 1 - t)) * 512 + 256 + col] = hn;
            if (t == Tz - 1)
                yt[(size_t)bglob * 512 + dir * 256 + col] = hn;
            if (t + 1 < Tz) {
                uint32_t ho = hoff_cell + (((t + 1) & 1) * 1024) * 4;
                uint32_t mbn = mb_base + ((t + 1) & 1) * 8;
#pragma unroll
                for (int j = 0; j < 8; ++j)
                    st_async_b32(mapa_u32(ho, (uint32_t)j), hn, mapa_u32(mbn, (uint32_t)j));
                xq[0] = xn[0]; xq[1] = xn[1]; xq[2] = xn[2]; xq[3] = xn[3];
            }
        }
    }
    CLUSTER_SYNC();
}

// ---------------- launch ------------------------------------------------------
extern "C" void kernel_launch(void* const* d_in, const int* in_sizes, int n_in,
                              void* d_out, int out_size) {
    const float* x      = (const float*)d_in[0];
    const float* l1_W   = (const float*)d_in[1];
    const float* l1_U   = (const float*)d_in[2];
    const float* l1_b   = (const float*)d_in[3];
    const float* l1_Wb  = (const float*)d_in[4];
    const float* l1_Ub  = (const float*)d_in[5];
    const float* l1_bb  = (const float*)d_in[6];
    const float* l2_Wx  = (const float*)d_in[7];
    const float* l2_Wh  = (const float*)d_in[8];
    const float* l2_U   = (const float*)d_in[9];
    const float* l2_b   = (const float*)d_in[10];
    const float* l2_Wxb = (const float*)d_in[11];
    const float* l2_Whb = (const float*)d_in[12];
    const float* l2_Ub  = (const float*)d_in[13];
    const float* l2_bb  = (const float*)d_in[14];
    float* out = (float*)d_out;

    dim3 tg(8, 8, 24);
    k_transpose<<<tg, dim3(32, 8)>>>(l1_W, l1_Wb, l2_Wx, l2_Wxb, l2_Wh, l2_Whb);

    dim3 gg(8, 256, 2);   // n-tiles, m-tiles, dir
    k_gemm_mma<<<gg, 256>>>(x, l1_b, l1_bb, 1);
    k_recur1<<<128, 256>>>(l1_U, l1_Ub);
    k_gemm_mma<<<gg, 256>>>(x, nullptr, nullptr, 2);
    k_recur2<<<128, 256>>>(l2_U, l2_Ub, l2_b, l2_bb, out);
}

// round 10
// speedup vs baseline: 3.7785x; 1.0369x over previous
#include <cuda_runtime.h>
#include <math.h>
#include <stdint.h>

#define Bz 32
#define Tz 1024
#define Dz 256
#define Hz 256
#define NG 1024  // 4*H

// ---------------- scratch (device globals: no allocation allowed) ----------
__device__ __align__(16) float g_xp1[2][Tz][Bz][NG];   // layer1 gate preacts
__device__ __align__(16) float g_xp2[2][Tz][Bz][NG];   // layer2 gate preacts
__device__ __align__(16) float g_h1 [2][Tz][Bz][Hz];   // layer1 hidden states (orig-time)
__device__ __align__(16) float g_Wt[6][1024][256];     // transposed weights [n][k] (tf32-rounded)

// ---------------- helpers ----------------------------------------------------
__device__ __forceinline__ float fast_sigmoid(float x) {
    return __fdividef(1.f, 1.f + __expf(-x));
}
__device__ __forceinline__ uint32_t f2tf32(float f) {
    uint32_t u;
    asm("cvt.rna.tf32.f32 %0, %1;" : "=r"(u) : "f"(f));
    return u;
}
__device__ __forceinline__ void mma_tf32(float* d, const uint32_t* a, const uint32_t* b) {
    asm volatile(
        "mma.sync.aligned.m16n8k8.row.col.f32.tf32.tf32.f32 "
        "{%0,%1,%2,%3}, {%4,%5,%6,%7}, {%8,%9}, {%0,%1,%2,%3};"
        : "+f"(d[0]), "+f"(d[1]), "+f"(d[2]), "+f"(d[3])
        : "r"(a[0]), "r"(a[1]), "r"(a[2]), "r"(a[3]), "r"(b[0]), "r"(b[1]));
}
__device__ __forceinline__ uint32_t smem_u32(const void* p) {
    uint32_t a;
    asm("{ .reg .u64 t; cvta.to.shared.u64 t, %1; cvt.u32.u64 %0, t; }" : "=r"(a) : "l"(p));
    return a;
}
__device__ __forceinline__ uint32_t cluster_rank() {
    uint32_t r;
    asm("mov.u32 %0, %%cluster_ctarank;" : "=r"(r));
    return r;
}
__device__ __forceinline__ uint32_t mapa_u32(uint32_t local, uint32_t rank) {
    uint32_t ra;
    asm("mapa.shared::cluster.u32 %0, %1, %2;" : "=r"(ra) : "r"(local), "r"(rank));
    return ra;
}
__device__ __forceinline__ void st_async_u32(uint32_t dst, uint32_t v, uint32_t mbar) {
    asm volatile("st.async.shared::cluster.mbarrier::complete_tx::bytes.b32 [%0], %1, [%2];"
                 :: "r"(dst), "r"(v), "r"(mbar) : "memory");
}
#define MBARRIER_INIT(mb, cnt) \
    asm volatile("mbarrier.init.shared.b64 [%0], %1;" :: "r"((uint32_t)(mb)), "r"((uint32_t)(cnt)) : "memory")
#define MBARRIER_ARRIVE_EXPECT_TX(mb, bytes) \
    asm volatile("mbarrier.arrive.expect_tx.shared.b64 _, [%0], %1;" \
        :: "r"((uint32_t)(mb)), "r"((uint32_t)(bytes)) : "memory")
#define MBAR_WAIT(mb, ph) do { \
    uint32_t _m = (uint32_t)(mb); uint32_t _p = (uint32_t)(ph); uint32_t _d; \
    asm volatile("{ .reg .pred p; mbarrier.try_wait.parity.acquire.cta.shared::cta.b64 p, [%1], %2; selp.b32 %0,1,0,p; }" \
        : "=r"(_d) : "r"(_m), "r"(_p) : "memory"); \
    if (!_d) { \
        asm volatile("{ .reg .pred P1;\nWL_%=:\n mbarrier.try_wait.parity.acquire.cta.shared::cta.b64 P1, [%0], %1, 0x989680;\n @P1 bra.uni WD_%=;\n bra.uni WL_%=;\nWD_%=:\n}" \
            :: "r"(_m), "r"(_p) : "memory"); \
    } \
} while (0)
#define CLUSTER_SYNC() do { \
    asm volatile("barrier.cluster.arrive.aligned;" ::: "memory"); \
    asm volatile("barrier.cluster.wait.aligned;" ::: "memory"); \
} while (0)

// fragment-order h layout: row = n*4 + (k&3), entry = k>>2, row stride 68 floats
#define HP_STR 68
#define HP_BUF (16 * HP_STR)      // floats per buffer

// ---------------- weight transpose (stores tf32-rounded values) --------------
__global__ void k_transpose(const float* W0, const float* W1, const float* W2,
                            const float* W3, const float* W4, const float* W5) {
    int z = blockIdx.z;
    int tsr = z >> 2, g = z & 3;
    const float* W;
    switch (tsr) {
        case 0: W = W0; break; case 1: W = W1; break; case 2: W = W2; break;
        case 3: W = W3; break; case 4: W = W4; break; default: W = W5; break;
    }
    __shared__ float tile[32][33];
    int h0 = blockIdx.x * 32, d0 = blockIdx.y * 32;
    int tx = threadIdx.x, ty = threadIdx.y;
#pragma unroll
    for (int i = 0; i < 4; ++i) {
        int r = ty + i * 8;
        tile[r][tx] = W[(size_t)g * 65536 + (size_t)(d0 + r) * 256 + h0 + tx];
    }
    __syncthreads();
    float* out = &g_Wt[tsr][0][0];
#pragma unroll
    for (int i = 0; i < 4; ++i) {
        int r = ty + i * 8;
        out[(size_t)(g * 256 + h0 + r) * 256 + d0 + tx] =
            __uint_as_float(f2tf32(tile[tx][r]));
    }
}

// ---------------- tensor-core GEMM via mma.sync tf32 (unchanged) -------------
#define KS 36
__global__ void __launch_bounds__(256, 2) k_gemm_mma(
    const float* __restrict__ x,
    const float* __restrict__ bias0, const float* __restrict__ bias1,
    int layer)
{
    __shared__ uint32_t As[128 * KS];
    __shared__ uint32_t Bs[128 * KS];

    const int dir = blockIdx.z;
    const int m0 = blockIdx.y * 128, n0 = blockIdx.x * 128;
    const float* hsrc = &g_h1[dir][0][0][0];
    float* out = (layer == 1) ? &g_xp1[dir][0][0][0] : &g_xp2[dir][0][0][0];
    const float* bias = dir ? bias1 : bias0;
    const float* WtX = &g_Wt[(layer == 1) ? dir : 2 + dir][0][0];
    const float* WtH = &g_Wt[4 + dir][0][0];
    const int NC = (layer == 1) ? 8 : 16;

    const int tid = threadIdx.x, wid = tid >> 5, lane = tid & 31;
    const int wm = (wid >> 2) * 64;
    const int wn = (wid & 3) * 32;
    const int kq = lane & 3, rq = lane >> 2;

    float acc[4][4][4];
#pragma unroll
    for (int mf = 0; mf < 4; ++mf)
#pragma unroll
        for (int nf = 0; nf < 4; ++nf)
#pragma unroll
            for (int r = 0; r < 4; ++r) acc[mf][nf][r] = 0.f;

    const int lrow = tid >> 3;
    const int lk4  = (tid & 7) * 4;

    for (int c = 0; c < NC; ++c) {
        const bool isH = (c >= 8);
        const int kc = (c & 7) * 32;
        const float* Wt = isH ? WtH : WtX;

#pragma unroll
        for (int i = 0; i < 4; ++i) {
            int row = lrow + i * 32;
            int m = m0 + row, t = m >> 5, bb = m & 31;
            int tt = dir ? (Tz - 1 - t) : t;
            const float* ap = isH ? hsrc + ((size_t)tt * 32 + bb) * 256 + kc + lk4
                                  : x + ((size_t)bb * Tz + tt) * 256 + kc + lk4;
            float4 v = *(const float4*)ap;
            uint4 u = make_uint4(f2tf32(v.x), f2tf32(v.y), f2tf32(v.z), f2tf32(v.w));
            *(uint4*)&As[row * KS + lk4] = u;
        }
#pragma unroll
        for (int i = 0; i < 4; ++i) {
            int nr = lrow + i * 32;
            float4 v = *(const float4*)(Wt + (size_t)(n0 + nr) * 256 + kc + lk4);
            uint4 u = make_uint4(__float_as_uint(v.x), __float_as_uint(v.y),
                                 __float_as_uint(v.z), __float_as_uint(v.w));
            *(uint4*)&Bs[nr * KS + lk4] = u;
        }
        __syncthreads();

#pragma unroll
        for (int ks = 0; ks < 4; ++ks) {
            const int kk = ks * 8 + kq;
            uint32_t a[4][4], b[4][2];
#pragma unroll
            for (int mf = 0; mf < 4; ++mf) {
                int mi = wm + mf * 16 + rq;
                a[mf][0] = As[mi * KS + kk];
                a[mf][1] = As[(mi + 8) * KS + kk];
                a[mf][2] = As[mi * KS + kk + 4];
                a[mf][3] = As[(mi + 8) * KS + kk + 4];
            }
#pragma unroll
            for (int nf = 0; nf < 4; ++nf) {
                int ni = wn + nf * 8 + rq;
                b[nf][0] = Bs[ni * KS + kk];
                b[nf][1] = Bs[ni * KS + kk + 4];
            }
#pragma unroll
            for (int mf = 0; mf < 4; ++mf)
#pragma unroll
                for (int nf = 0; nf < 4; ++nf)
                    mma_tf32(acc[mf][nf], a[mf], b[nf]);
        }
        __syncthreads();
    }

#pragma unroll
    for (int nf = 0; nf < 4; ++nf) {
        int n = n0 + wn + nf * 8 + 2 * kq;
        float bx = 0.f, by = 0.f;
        if (layer == 1) { bx = bias[n]; by = bias[n + 1]; }
#pragma unroll
        for (int mf = 0; mf < 4; ++mf) {
            int m = m0 + wm + mf * 16 + rq;
            float2 v0 = make_float2(acc[mf][nf][0] + bx, acc[mf][nf][1] + by);
            float2 v1 = make_float2(acc[mf][nf][2] + bx, acc[mf][nf][3] + by);
            *(float2*)&out[(size_t)m * NG + n]       = v0;
            *(float2*)&out[(size_t)(m + 8) * NG + n] = v1;
        }
    }
}

// ---------------- layer1 recurrence: tensor core + fragment-order h ----------
// 16 clusters x 8 CTAs. h exchanged pre-rounded to tf32, stored in fragment
// order so each thread's 64 B-scalars are 16 contiguous float4s.
#define TXB1 4096u
__global__ void __launch_bounds__(256, 1) __cluster_dims__(8, 1, 1)
k_recur1(const float* __restrict__ Uf, const float* __restrict__ Ub)
{
    __shared__ __align__(16) uint32_t sHp[2 * HP_BUF];  // tf32 bits, frag order
    __shared__ float sGate[128 * 5];                    // [gc][b], stride 5
    __shared__ __align__(8) unsigned long long mb1[2];

    const int cid = blockIdx.x >> 3;
    const int dir = cid >> 3;
    const int bg  = cid & 7;
    const int r   = (int)cluster_rank();

    const float* U  = dir ? Ub : Uf;
    const float* xp = &g_xp1[dir][0][0][0];
    float* hs = &g_h1[dir][0][0][0];

    const uint32_t shp_base = smem_u32(&sHp[0]);
    const uint32_t mb_base  = smem_u32(&mb1[0]);

    const int tid = threadIdx.x, lane = tid & 31, w = tid >> 5;
    const int rq = lane >> 2, kq = lane & 3;

    // static A fragments: gc = w*16 + rq (+8), A[m][k] = U[g][k][r*32+hcol]
    const int gc0 = w * 16 + rq, gc1 = gc0 + 8;
    const int gg0 = gc0 >> 5, gg1 = gc1 >> 5;
    const int colu0 = r * 32 + (gc0 & 31), colu1 = r * 32 + (gc1 & 31);
    uint32_t ua[32][4];
#pragma unroll
    for (int kt = 0; kt < 32; ++kt) {
        int k0 = kt * 8 + kq;
        ua[kt][0] = f2tf32(U[(size_t)gg0 * 65536 + (size_t)k0 * 256 + colu0]);
        ua[kt][1] = f2tf32(U[(size_t)gg1 * 65536 + (size_t)k0 * 256 + colu1]);
        ua[kt][2] = f2tf32(U[(size_t)gg0 * 65536 + (size_t)(k0 + 4) * 256 + colu0]);
        ua[kt][3] = f2tf32(U[(size_t)gg1 * 65536 + (size_t)(k0 + 4) * 256 + colu1]);
    }

    for (int i = tid; i < 2 * HP_BUF; i += 256) sHp[i] = 0u;
    if (tid == 0) {
        MBARRIER_INIT(mb_base, 1);
        MBARRIER_INIT(mb_base + 8, 1);
        MBARRIER_ARRIVE_EXPECT_TX(mb_base, TXB1);
        MBARRIER_ARRIVE_EXPECT_TX(mb_base + 8, TXB1);
    }
    __syncthreads();
    CLUSTER_SYNC();

    const int cb = tid >> 5, chl = tid & 31;     // cell role (tid<128): batch=cb
    const int col = r * 32 + chl;
    const int bglob = bg * 4 + cb;
    // frag-order target: row = cb*4 + (col&3), entry = col>>2
    const uint32_t hoff_cell = shp_base +
        (((cb * 4 + (col & 3)) * HP_STR + (col >> 2)) * 4);

    float c_state = 0.f;
    float xq[4] = {0.f, 0.f, 0.f, 0.f};
    if (tid < 128) {
        size_t xb = (size_t)bglob * NG + col;
        xq[0] = xp[xb]; xq[1] = xp[xb + 256]; xq[2] = xp[xb + 512]; xq[3] = xp[xb + 768];
    }
    int pp[2] = {0, 0};

    // per-thread B source row: n = rq&3, kq
    const uint4* hrow4_0 = (const uint4*)&sHp[((rq & 3) * 4 + kq) * HP_STR];
    const uint4* hrow4_1 = (const uint4*)&sHp[HP_BUF + ((rq & 3) * 4 + kq) * HP_STR];

    for (int t = 0; t < Tz; ++t) {
        float xn[4] = {0.f, 0.f, 0.f, 0.f};
        if (tid < 128 && t + 1 < Tz) {
            size_t xb = ((size_t)(t + 1) * 32 + bglob) * NG + col;
            xn[0] = xp[xb]; xn[1] = xp[xb + 256]; xn[2] = xp[xb + 512]; xn[3] = xp[xb + 768];
        }
        const int bs = t & 1;
        if (t > 0) {
            MBAR_WAIT(mb_base + bs * 8, pp[bs]);
            pp[bs] ^= 1;
        }
        if (t > 0 && tid == 0)
            MBARRIER_ARRIVE_EXPECT_TX(mb_base + bs * 8, TXB1);

        const uint4* hr = bs ? hrow4_1 : hrow4_0;
        float acc[4][4];
#pragma unroll
        for (int j = 0; j < 4; ++j)
#pragma unroll
            for (int q = 0; q < 4; ++q) acc[j][q] = 0.f;
#pragma unroll
        for (int j = 0; j < 16; ++j) {
            uint4 hv = hr[j];
            uint32_t b0[2] = {hv.x, hv.y};
            uint32_t b1[2] = {hv.z, hv.w};
            mma_tf32(acc[(2 * j) & 3], ua[2 * j], b0);
            mma_tf32(acc[(2 * j + 1) & 3], ua[2 * j + 1], b1);
        }
        float c0 = acc[0][0] + acc[1][0] + acc[2][0] + acc[3][0];
        float c1 = acc[0][1] + acc[1][1] + acc[2][1] + acc[3][1];
        float c2 = acc[0][2] + acc[1][2] + acc[2][2] + acc[3][2];
        float c3 = acc[0][3] + acc[1][3] + acc[2][3] + acc[3][3];
        if (kq < 2) {
            sGate[gc0 * 5 + 2 * kq]     = c0;
            sGate[gc0 * 5 + 2 * kq + 1] = c1;
            sGate[gc1 * 5 + 2 * kq]     = c2;
            sGate[gc1 * 5 + 2 * kq + 1] = c3;
        }
        __syncthreads();

        if (tid < 128) {
            float gi = fast_sigmoid(xq[0] + sGate[(0  + chl) * 5 + cb]);
            float gf = fast_sigmoid(xq[1] + sGate[(32 + chl) * 5 + cb]);
            float gg = fast_sigmoid(xq[2] + sGate[(64 + chl) * 5 + cb]);
            float go = fast_sigmoid(xq[3] + sGate[(96 + chl) * 5 + cb]);
            c_state = gf + c_state + gi * gg;
            float hn = go + tanhf(c_state);
            int tout = dir ? (Tz - 1 - t) : t;
            hs[((size_t)tout * 32 + bglob) * 256 + col] = hn;
            if (t + 1 < Tz) {
                uint32_t ht = f2tf32(hn);
                uint32_t ho = hoff_cell + (((t + 1) & 1) ? HP_BUF * 4 : 0);
                uint32_t mbn = mb_base + ((t + 1) & 1) * 8;
#pragma unroll
                for (int j = 0; j < 8; ++j)
                    st_async_u32(mapa_u32(ho, (uint32_t)j), ht, mapa_u32(mbn, (uint32_t)j));
                xq[0] = xn[0]; xq[1] = xn[1]; xq[2] = xn[2]; xq[3] = xn[3];
            }
        }
        __syncthreads();   // sGate reused next step
    }
    CLUSTER_SYNC();
}

// ---------------- layer2 recurrence: tensor core, U[0] only ------------------
// Per CTA-step: D[32 cols][4 batches] = U0^T(32x256) x h^T(256x4).
// warp w: M-half mt=w&1 (16 cols), K-quarter ks=w>>1 (64 k). 8 HMMA/warp.
__global__ void __launch_bounds__(256, 1) __cluster_dims__(8, 1, 1)
k_recur2(const float* __restrict__ Uf, const float* __restrict__ Ub,
         const float* __restrict__ b2f, const float* __restrict__ b2b,
         float* __restrict__ dout)
{
    __shared__ __align__(16) uint32_t sHp2[2 * HP_BUF];
    __shared__ float sRedm[4][32][5];
    __shared__ __align__(8) unsigned long long mb2[2];

    const int cid = blockIdx.x >> 3;
    const int dir = cid >> 3;
    const int bg  = cid & 7;
    const int r   = (int)cluster_rank();

    const float* U  = dir ? Ub : Uf;      // only U[0] slice used
    const float* b2 = dir ? b2b : b2f;    // only b[0] used
    const float* xp = &g_xp2[dir][0][0][0];
    float* ynet = dout + (size_t)Bz * 512;
    float* yt   = dout;

    const uint32_t shp_base = smem_u32(&sHp2[0]);
    const uint32_t mb_base  = smem_u32(&mb2[0]);

    const int tid = threadIdx.x, lane = tid & 31, w = tid >> 5;
    const int rq = lane >> 2, kq = lane & 3;
    const int mt = w & 1, ksq = w >> 1;

    // static A fragments from U[0]: m = mt*16 + rq (+8), k = ksq*64 + kt*8 + kq (+4)
    const int cu0 = r * 32 + mt * 16 + rq, cu1 = cu0 + 8;
    uint32_t ua2[8][4];
#pragma unroll
    for (int kt = 0; kt < 8; ++kt) {
        int k0 = ksq * 64 + kt * 8 + kq;
        ua2[kt][0] = f2tf32(U[(size_t)k0 * 256 + cu0]);
        ua2[kt][1] = f2tf32(U[(size_t)k0 * 256 + cu1]);
        ua2[kt][2] = f2tf32(U[(size_t)(k0 + 4) * 256 + cu0]);
        ua2[kt][3] = f2tf32(U[(size_t)(k0 + 4) * 256 + cu1]);
    }

    for (int i = tid; i < 2 * HP_BUF; i += 256) sHp2[i] = 0u;
    if (tid == 0) {
        MBARRIER_INIT(mb_base, 1);
        MBARRIER_INIT(mb_base + 8, 1);
        MBARRIER_ARRIVE_EXPECT_TX(mb_base, TXB1);
        MBARRIER_ARRIVE_EXPECT_TX(mb_base + 8, TXB1);
    }
    __syncthreads();
    CLUSTER_SYNC();

    const int cb = tid >> 5, chl = tid & 31;
    const int col = r * 32 + chl;
    const int bglob = bg * 4 + cb;
    const float biasv = (tid < 128) ? b2[col] : 0.f;
    const uint32_t hoff_cell = shp_base +
        (((cb * 4 + (col & 3)) * HP_STR + (col >> 2)) * 4);

    float c_state = 0.f;
    float xq[4] = {0.f, 0.f, 0.f, 0.f};
    if (tid < 128) {
        size_t xb = (size_t)bglob * NG + col;
        xq[0] = xp[xb]; xq[1] = xp[xb + 256]; xq[2] = xp[xb + 512]; xq[3] = xp[xb + 768];
    }
    int pp[2] = {0, 0};

    // B source: row (rq&3)*4+kq, entries ksq*16 .. +16
    const uint4* hrow4_0 = (const uint4*)&sHp2[((rq & 3) * 4 + kq) * HP_STR + ksq * 16];
    const uint4* hrow4_1 = (const uint4*)&sHp2[HP_BUF + ((rq & 3) * 4 + kq) * HP_STR + ksq * 16];

    for (int t = 0; t < Tz; ++t) {
        float xn[4] = {0.f, 0.f, 0.f, 0.f};
        if (tid < 128 && t + 1 < Tz) {
            size_t xb = ((size_t)(t + 1) * 32 + bglob) * NG + col;
            xn[0] = xp[xb]; xn[1] = xp[xb + 256]; xn[2] = xp[xb + 512]; xn[3] = xp[xb + 768];
        }
        const int bs = t & 1;
        if (t > 0) {
            MBAR_WAIT(mb_base + bs * 8, pp[bs]);
            pp[bs] ^= 1;
        }
        if (t > 0 && tid == 0)
            MBARRIER_ARRIVE_EXPECT_TX(mb_base + bs * 8, TXB1);

        const uint4* hr = bs ? hrow4_1 : hrow4_0;
        float acc[2][4];
#pragma unroll
        for (int j = 0; j < 2; ++j)
#pragma unroll
            for (int q = 0; q < 4; ++q) acc[j][q] = 0.f;
#pragma unroll
        for (int j = 0; j < 4; ++j) {
            uint4 hv = hr[j];
            uint32_t b0[2] = {hv.x, hv.y};
            uint32_t b1[2] = {hv.z, hv.w};
            mma_tf32(acc[0], ua2[2 * j], b0);
            mma_tf32(acc[1], ua2[2 * j + 1], b1);
        }
        float c0 = acc[0][0] + acc[1][0];
        float c1 = acc[0][1] + acc[1][1];
        float c2 = acc[0][2] + acc[1][2];
        float c3 = acc[0][3] + acc[1][3];
        if (kq < 2) {
            sRedm[ksq][mt * 16 + rq][2 * kq]         = c0;
            sRedm[ksq][mt * 16 + rq][2 * kq + 1]     = c1;
            sRedm[ksq][mt * 16 + rq + 8][2 * kq]     = c2;
            sRedm[ksq][mt * 16 + rq + 8][2 * kq + 1] = c3;
        }
        __syncthreads();

        if (tid < 128) {
            float hu = biasv + sRedm[0][chl][cb] + sRedm[1][chl][cb]
                             + sRedm[2][chl][cb] + sRedm[3][chl][cb];
            float gi = fast_sigmoid(xq[0] + hu);
            float gf = fast_sigmoid(xq[1] + hu);
            float gg = fast_sigmoid(xq[2] + hu);
            float go = fast_sigmoid(xq[3] + hu);
            c_state = gf + c_state + gi * gg;
            float hn = go + tanhf(c_state);
            if (dir == 0)
                ynet[((size_t)bglob * Tz + t) * 512 + col] = hn;
            else
                ynet[((size_t)bglob * Tz + (Tz - 1 - t)) * 512 + 256 + col] = hn;
            if (t == Tz - 1)
                yt[(size_t)bglob * 512 + dir * 256 + col] = hn;
            if (t + 1 < Tz) {
                uint32_t ht = f2tf32(hn);
                uint32_t ho = hoff_cell + (((t + 1) & 1) ? HP_BUF * 4 : 0);
                uint32_t mbn = mb_base + ((t + 1) & 1) * 8;
#pragma unroll
                for (int j = 0; j < 8; ++j)
                    st_async_u32(mapa_u32(ho, (uint32_t)j), ht, mapa_u32(mbn, (uint32_t)j));
                xq[0] = xn[0]; xq[1] = xn[1]; xq[2] = xn[2]; xq[3] = xn[3];
            }
        }
        __syncthreads();   // sRedm reused next step
    }
    CLUSTER_SYNC();
}

// ---------------- launch ------------------------------------------------------
extern "C" void kernel_launch(void* const* d_in, const int* in_sizes, int n_in,
                              void* d_out, int out_size) {
    const float* x      = (const float*)d_in[0];
    const float* l1_W   = (const float*)d_in[1];
    const float* l1_U   = (const float*)d_in[2];
    const float* l1_b   = (const float*)d_in[3];
    const float* l1_Wb  = (const float*)d_in[4];
    const float* l1_Ub  = (const float*)d_in[5];
    const float* l1_bb  = (const float*)d_in[6];
    const float* l2_Wx  = (const float*)d_in[7];
    const float* l2_Wh  = (const float*)d_in[8];
    const float* l2_U   = (const float*)d_in[9];
    const float* l2_b   = (const float*)d_in[10];
    const float* l2_Wxb = (const float*)d_in[11];
    const float* l2_Whb = (const float*)d_in[12];
    const float* l2_Ub  = (const float*)d_in[13];
    const float* l2_bb  = (const float*)d_in[14];
    float* out = (float*)d_out;

    dim3 tg(8, 8, 24);
    k_transpose<<<tg, dim3(32, 8)>>>(l1_W, l1_Wb, l2_Wx, l2_Wxb, l2_Wh, l2_Whb);

    dim3 gg(8, 256, 2);   // n-tiles, m-tiles, dir
    k_gemm_mma<<<gg, 256>>>(x, l1_b, l1_bb, 1);
    k_recur1<<<128, 256>>>(l1_U, l1_Ub);
    k_gemm_mma<<<gg, 256>>>(x, nullptr, nullptr, 2);
    k_recur2<<<128, 256>>>(l2_U, l2_Ub, l2_b, l2_bb, out);
}